// round 13
// baseline (speedup 1.0000x reference)
#include <cuda_runtime.h>
#include <cuda_bf16.h>
#include <math.h>
#include <stdint.h>

// Problem constants
#define Bq 8
#define Tq 2048
#define Dq 1024
#define Hq 16
#define Kq 64
#define Mq (Bq*Tq)                 // 16384 rows
#define BTDq ((size_t)Mq*(size_t)Dq)

// ---------------- scratch (device globals; no allocations allowed) -------------
__device__ float g_dx  [Mq*Dq];
__device__ float g_t5  [Mq*160];
__device__ float g_xw  [Mq*Dq];
__device__ float g_r   [Mq*Dq];
__device__ float g_k   [Mq*Dq];
__device__ float g_v   [Mq*Dq];
__device__ float g_g   [Mq*Dq];
__device__ float g_hbuf[Mq*64];
__device__ float g_ww  [Mq*Dq];
__device__ float g_gate[Mq*Dq];
__device__ float g_yf  [Mq*Dq];
__device__ float g_yb  [Mq*Dq];

// bf16 hi/lo split activations
__device__ __nv_bfloat16 g_xxh[Mq*Dq], g_xxl[Mq*Dq];
__device__ __nv_bfloat16 g_dxh[Mq*Dq], g_dxl[Mq*Dq];
__device__ __nv_bfloat16 g_xkh[Mq*Dq], g_xkl[Mq*Dq];
__device__ __nv_bfloat16 g_xvh[Mq*Dq], g_xvl[Mq*Dq];
__device__ __nv_bfloat16 g_xrh[Mq*Dq], g_xrl[Mq*Dq];
__device__ __nv_bfloat16 g_xgh[Mq*Dq], g_xgl[Mq*Dq];
__device__ __nv_bfloat16 g_zh [Mq*Dq], g_zl [Mq*Dq];
// transposed weights [N,K] hi/lo, 6 slots: Wr,Wk,Wv,Wg,gate_w,Wo
__device__ __nv_bfloat16 g_wh[6*1024*1024], g_wl[6*1024*1024];
// maa_w1 transposed [160(+pad to 256),1024] hi/lo
__device__ __nv_bfloat16 g_w1h[256*1024], g_w1l[256*1024];

// ---------------- helpers -------------------------------------------------------
__device__ __forceinline__ uint32_t smem_u32(const void* p) {
    uint32_t a;
    asm("{ .reg .u64 t; cvta.to.shared.u64 t, %1; cvt.u32.u64 %0, t; }" : "=r"(a) : "l"(p));
    return a;
}
__device__ __forceinline__ void cp16(uint32_t dst, const void* src) {
    asm volatile("cp.async.cg.shared.global [%0], [%1], 16;" :: "r"(dst), "l"(src));
}
__device__ __forceinline__ void cp4(uint32_t dst, const void* src) {
    asm volatile("cp.async.ca.shared.global [%0], [%1], 4;" :: "r"(dst), "l"(src));
}
#define CP_COMMIT() asm volatile("cp.async.commit_group;" ::: "memory")
#define CP_WAIT(n)  asm volatile("cp.async.wait_group %0;" :: "n"(n) : "memory")

#define LDSM4(R0, R1, R2, R3, ADDR) \
    asm volatile("ldmatrix.sync.aligned.m8n8.x4.shared.b16 {%0,%1,%2,%3}, [%4];" \
        : "=r"(R0), "=r"(R1), "=r"(R2), "=r"(R3) : "r"(ADDR))

#define MMA_BF16(D, A, B0, B1) \
    asm volatile("mma.sync.aligned.m16n8k16.row.col.f32.bf16.bf16.f32 " \
        "{%0,%1,%2,%3}, {%4,%5,%6,%7}, {%8,%9}, {%0,%1,%2,%3};" \
        : "+f"((D)[0]), "+f"((D)[1]), "+f"((D)[2]), "+f"((D)[3]) \
        : "r"((A)[0]), "r"((A)[1]), "r"((A)[2]), "r"((A)[3]), "r"(B0), "r"(B1))

// packed f32x2 helpers
__device__ __forceinline__ unsigned long long pk2(float lo, float hi) {
    unsigned long long r;
    asm("mov.b64 %0, {%1, %2};" : "=l"(r) : "f"(lo), "f"(hi));
    return r;
}
__device__ __forceinline__ void fma2(unsigned long long& d,
                                     unsigned long long a,
                                     unsigned long long b) {
    asm("fma.rn.f32x2 %0, %1, %2, %0;" : "+l"(d) : "l"(a), "l"(b));
}
__device__ __forceinline__ unsigned long long fma2v(unsigned long long a,
                                                    unsigned long long b,
                                                    unsigned long long c) {
    unsigned long long d;
    asm("fma.rn.f32x2 %0, %1, %2, %3;" : "=l"(d) : "l"(a), "l"(b), "l"(c));
    return d;
}
__device__ __forceinline__ unsigned long long mul2(unsigned long long a,
                                                   unsigned long long b) {
    unsigned long long d;
    asm("mul.rn.f32x2 %0, %1, %2;" : "=l"(d) : "l"(a), "l"(b));
    return d;
}
__device__ __forceinline__ void unpk2(unsigned long long v, float& lo, float& hi) {
    asm("mov.b64 {%0, %1}, %2;" : "=f"(lo), "=f"(hi) : "l"(v));
}

// hi/lo split store of 4 consecutive floats
__device__ __forceinline__ void store_split4(__nv_bfloat16* H, __nv_bfloat16* L,
                                             size_t idx, float4 o) {
    __nv_bfloat162 h01 = __floats2bfloat162_rn(o.x, o.y);
    __nv_bfloat162 h23 = __floats2bfloat162_rn(o.z, o.w);
    float2 f01 = __bfloat1622float2(h01);
    float2 f23 = __bfloat1622float2(h23);
    __nv_bfloat162 l01 = __floats2bfloat162_rn(o.x - f01.x, o.y - f01.y);
    __nv_bfloat162 l23 = __floats2bfloat162_rn(o.z - f23.x, o.w - f23.y);
    uint2 hv = make_uint2(*(unsigned*)&h01, *(unsigned*)&h23);
    uint2 lv = make_uint2(*(unsigned*)&l01, *(unsigned*)&l23);
    *(uint2*)&H[idx] = hv;
    *(uint2*)&L[idx] = lv;
}

// ---------------- kernel: depthwise conv (k=3), dx fp32+hi/lo, xxx hi/lo -------
__global__ void conv_kernel(const float* __restrict__ x,
                            const float* __restrict__ cw,
                            const float* __restrict__ maa_x)
{
    size_t idx = (size_t)blockIdx.x * blockDim.x + threadIdx.x;
    if (idx >= BTDq) return;
    int d = (int)(idx & (Dq - 1));
    int t = (int)((idx / Dq) & (Tq - 1));
    float x0 = x[idx];
    float xm = (t > 0)      ? x[idx - Dq] : 0.f;
    float xp = (t < Tq - 1) ? x[idx + Dq] : 0.f;
    float dxv = cw[d*3+0]*xm + cw[d*3+1]*x0 + cw[d*3+2]*xp - x0;
    float xxx = x0 + dxv * maa_x[d];
    g_dx[idx] = dxv;
    __nv_bfloat16 h = __float2bfloat16(dxv);
    g_dxh[idx] = h;
    g_dxl[idx] = __float2bfloat16(dxv - __bfloat162float(h));
    __nv_bfloat16 xh = __float2bfloat16(xxx);
    g_xxh[idx] = xh;
    g_xxl[idx] = __float2bfloat16(xxx - __bfloat162float(xh));
}

// ---------------- kernel: weight transpose + bf16 split (6 slots) --------------
__global__ void __launch_bounds__(256) wsplit_kernel(
    const float* __restrict__ W0, const float* __restrict__ W1,
    const float* __restrict__ W2, const float* __restrict__ W3,
    const float* __restrict__ W4, const float* __restrict__ W5)
{
    __shared__ float tile[32][33];
    const float* Ws[6] = { W0, W1, W2, W3, W4, W5 };
    const float* W = Ws[blockIdx.z];
    __nv_bfloat16* H = g_wh + (size_t)blockIdx.z * 1024 * 1024;
    __nv_bfloat16* L = g_wl + (size_t)blockIdx.z * 1024 * 1024;
    int n0 = blockIdx.x * 32, k0 = blockIdx.y * 32;
    int tx = threadIdx.x & 31, ty = threadIdx.x >> 5;
    #pragma unroll
    for (int i = 0; i < 4; i++)
        tile[ty + i*8][tx] = W[(size_t)(k0 + ty + i*8) * 1024 + n0 + tx];
    __syncthreads();
    #pragma unroll
    for (int i = 0; i < 4; i++) {
        float v = tile[tx][ty + i*8];
        __nv_bfloat16 h = __float2bfloat16(v);
        size_t o = (size_t)(n0 + ty + i*8) * 1024 + k0 + tx;
        H[o] = h;
        L[o] = __float2bfloat16(v - __bfloat162float(h));
    }
}

// ---------------- kernel: maa_w1 [1024,160] -> [160,1024] hi/lo ----------------
__global__ void __launch_bounds__(256) wsplit_w1_kernel(const float* __restrict__ W1)
{
    __shared__ float tile[32][33];
    int n0 = blockIdx.x * 32, k0 = blockIdx.y * 32;   // n<160, k<1024
    int tx = threadIdx.x & 31, ty = threadIdx.x >> 5;
    #pragma unroll
    for (int i = 0; i < 4; i++)
        tile[ty + i*8][tx] = W1[(size_t)(k0 + ty + i*8) * 160 + n0 + tx];
    __syncthreads();
    #pragma unroll
    for (int i = 0; i < 4; i++) {
        float v = tile[tx][ty + i*8];
        __nv_bfloat16 h = __float2bfloat16(v);
        size_t o = (size_t)(n0 + ty + i*8) * 1024 + k0 + tx;
        g_w1h[o] = h;
        g_w1l[o] = __float2bfloat16(v - __bfloat162float(h));
    }
}

// ---------------- HMMA bf16 split GEMM (mma.sync), 3-stage pipeline ------------
// PASSES=3: AhBh + AhBl + AlBh.  PASSES=4: + AlBl
#define HM_SMEM 98304
enum { TEPI_NONE = 0, TEPI_SILU, TEPI_GATE, TEPI_TANH };

template<int EPI>
__device__ __forceinline__ float tepi(float a, int col, const float* __restrict__ vec) {
    if (EPI == TEPI_SILU) return a / (1.f + __expf(-a));
    if (EPI == TEPI_GATE) return 1.f / (1.f + __expf(-(a + vec[col])));
    if (EPI == TEPI_TANH) return tanhf(a);
    return a;
}

template<int EPI, int PASSES>
__global__ void __launch_bounds__(256, 1) hmma_gemm(
    const __nv_bfloat16* __restrict__ Ah, const __nv_bfloat16* __restrict__ Al,
    const __nv_bfloat16* __restrict__ Bh, const __nv_bfloat16* __restrict__ Bl,
    float* __restrict__ C, const float* __restrict__ vec,
    int N, int ldc)
{
    extern __shared__ __align__(128) char sm[];
    const uint32_t sb = smem_u32(sm);
    const int tid = threadIdx.x, lane = tid & 31, wid = tid >> 5;
    const int m0 = blockIdx.y * 128, n0 = blockIdx.x * 128;
    const int wm = (wid & 1) * 64;
    const int wn = (wid >> 1) * 32;

    const int ldrow = (tid >> 2);
    const int ldk16 = tid & 3;

    float acc[4][4][4];
    #pragma unroll
    for (int a = 0; a < 4; a++)
        #pragma unroll
        for (int b = 0; b < 4; b++)
            #pragma unroll
            for (int c = 0; c < 4; c++) acc[a][b][c] = 0.f;

    auto load_chunk = [&](int c) {
        const uint32_t base = sb + (uint32_t)(c % 3) * 32768;
        const int kc = c * 32;
        #pragma unroll
        for (int h = 0; h < 2; h++) {
            int row = ldrow + h * 64;
            uint32_t sw = (uint32_t)row * 64 + (uint32_t)((ldk16 ^ ((row >> 1) & 3)) << 4);
            size_t ga = (size_t)(m0 + row) * 1024 + kc + ldk16 * 8;
            size_t gb = (size_t)(n0 + row) * 1024 + kc + ldk16 * 8;
            cp16(base +         sw, Ah + ga);
            cp16(base +  8192 + sw, Al + ga);
            cp16(base + 16384 + sw, Bh + gb);
            cp16(base + 24576 + sw, Bl + gb);
        }
        CP_COMMIT();
    };

    load_chunk(0);
    load_chunk(1);

    const int rowl = lane & 15;
    const int s3 = (rowl >> 1) & 3;
    const int chnk = lane >> 4;
    // precomputed swizzle offsets for ks=0,1
    const uint32_t sw0 = (uint32_t)(((chnk) ^ s3) << 4);
    const uint32_t sw1 = (uint32_t)(((2 + chnk) ^ s3) << 4);

    for (int c = 0; c < 32; c++) {
        CP_WAIT(1);
        __syncthreads();
        if (c + 2 < 32) load_chunk(c + 2);

        const uint32_t st = sb + (uint32_t)(c % 3) * 32768;
        const uint32_t aBase = st + (uint32_t)(wm + rowl) * 64;
        const uint32_t bBase = st + 16384 + (uint32_t)(wn + rowl) * 64;

        #pragma unroll
        for (int ks = 0; ks < 2; ks++) {
            const uint32_t sw = (ks == 0) ? sw0 : sw1;
            uint32_t ah[4][4], al[4][4], bh[2][4], bl[2][4];
            #pragma unroll
            for (int mi = 0; mi < 4; mi++) {
                LDSM4(ah[mi][0], ah[mi][1], ah[mi][2], ah[mi][3], aBase + mi * 1024 + sw);
                LDSM4(al[mi][0], al[mi][1], al[mi][2], al[mi][3], aBase + 8192 + mi * 1024 + sw);
            }
            #pragma unroll
            for (int nf = 0; nf < 2; nf++) {
                LDSM4(bh[nf][0], bh[nf][1], bh[nf][2], bh[nf][3], bBase + nf * 1024 + sw);
                LDSM4(bl[nf][0], bl[nf][1], bl[nf][2], bl[nf][3], bBase + 8192 + nf * 1024 + sw);
            }
            #pragma unroll
            for (int mi = 0; mi < 4; mi++) {
                #pragma unroll
                for (int nj = 0; nj < 4; nj++) {
                    uint32_t b0h = bh[nj >> 1][nj & 1], b1h = bh[nj >> 1][(nj & 1) + 2];
                    uint32_t b0l = bl[nj >> 1][nj & 1], b1l = bl[nj >> 1][(nj & 1) + 2];
                    MMA_BF16(acc[mi][nj], ah[mi], b0h, b1h);
                    MMA_BF16(acc[mi][nj], ah[mi], b0l, b1l);
                    MMA_BF16(acc[mi][nj], al[mi], b0h, b1h);
                    if (PASSES == 4) MMA_BF16(acc[mi][nj], al[mi], b0l, b1l);
                }
            }
        }
    }

    const int er = lane >> 2, ec = (lane & 3) * 2;
    #pragma unroll
    for (int mi = 0; mi < 4; mi++) {
        #pragma unroll
        for (int nj = 0; nj < 4; nj++) {
            int row = m0 + wm + mi * 16 + er;
            int col = n0 + wn + nj * 8 + ec;
            if (col < N) {
                float2 o0, o1;
                o0.x = tepi<EPI>(acc[mi][nj][0], col,     vec);
                o0.y = tepi<EPI>(acc[mi][nj][1], col + 1, vec);
                o1.x = tepi<EPI>(acc[mi][nj][2], col,     vec);
                o1.y = tepi<EPI>(acc[mi][nj][3], col + 1, vec);
                *(float2*)&C[(size_t)row * ldc + col]       = o0;
                *(float2*)&C[(size_t)(row + 8) * ldc + col] = o1;
            }
        }
    }
}

// ---------------- scalar SGEMM (FFMA2) for decay GEMMs (fp32 precision) --------
#define BMt 128
#define BNt 128
#define BKt 16
enum { EPI_NONE = 0, EPI_TANH, EPI_DECAY };

template<int EPI>
__device__ __forceinline__ float epi_apply(float acc, int col,
                                           const float* __restrict__ vec)
{
    if (EPI == EPI_TANH)  return tanhf(acc);
    if (EPI == EPI_DECAY) return __expf(-__expf(vec[col] + acc));
    return acc;
}

template<int EPI>
__global__ void __launch_bounds__(256, 2) sgemm(
    const float* __restrict__ A, int lda,
    const float* __restrict__ Bm, int ldb,
    float* __restrict__ C, int ldc,
    int N, int Kd,
    const float* __restrict__ vec)
{
    __shared__ float As[BKt][BMt];
    __shared__ float Bs[BKt][BNt];

    int tid = threadIdx.x;
    int m0  = blockIdx.y * BMt;
    int n0  = blockIdx.x * BNt;

    int a_row = tid >> 2;
    int a_col = (tid & 3) << 2;
    int b_row = tid >> 5;
    int b_col = (tid & 31) << 2;
    int ty = tid >> 4, tx = tid & 15;

    const float* Aptr = A + (size_t)m0 * lda;
    bool bvalid = (n0 + b_col) < N;
    const float4 z4 = make_float4(0.f, 0.f, 0.f, 0.f);

    float4 a_reg[2], b_reg[2];
    a_reg[0] = *(const float4*)(Aptr + (size_t)a_row       * lda + a_col);
    a_reg[1] = *(const float4*)(Aptr + (size_t)(a_row + 64) * lda + a_col);
    b_reg[0] = bvalid ? *(const float4*)(Bm + (size_t)b_row       * ldb + n0 + b_col) : z4;
    b_reg[1] = bvalid ? *(const float4*)(Bm + (size_t)(b_row + 8) * ldb + n0 + b_col) : z4;

    #pragma unroll
    for (int jj = 0; jj < 4; jj++) {
        As[a_col + jj][a_row]      = ((const float*)&a_reg[0])[jj];
        As[a_col + jj][a_row + 64] = ((const float*)&a_reg[1])[jj];
    }
    *(float4*)&Bs[b_row][b_col]     = b_reg[0];
    *(float4*)&Bs[b_row + 8][b_col] = b_reg[1];
    __syncthreads();

    unsigned long long acc2[8][4];
    #pragma unroll
    for (int i = 0; i < 8; i++)
        #pragma unroll
        for (int j = 0; j < 4; j++)
            acc2[i][j] = 0ull;

    for (int k0 = 0;;) {
        int knext = k0 + BKt;
        if (knext < Kd) {
            a_reg[0] = *(const float4*)(Aptr + (size_t)a_row       * lda + knext + a_col);
            a_reg[1] = *(const float4*)(Aptr + (size_t)(a_row + 64) * lda + knext + a_col);
            b_reg[0] = bvalid ? *(const float4*)(Bm + (size_t)(knext + b_row)     * ldb + n0 + b_col) : z4;
            b_reg[1] = bvalid ? *(const float4*)(Bm + (size_t)(knext + b_row + 8) * ldb + n0 + b_col) : z4;
        }
        #pragma unroll
        for (int kk = 0; kk < BKt; kk++) {
            float a_f[8], b_f[8];
            *(float4*)&a_f[0] = *(const float4*)&As[kk][ty * 8];
            *(float4*)&a_f[4] = *(const float4*)&As[kk][ty * 8 + 4];
            *(float4*)&b_f[0] = *(const float4*)&Bs[kk][tx * 8];
            *(float4*)&b_f[4] = *(const float4*)&Bs[kk][tx * 8 + 4];
            unsigned long long b2[4];
            #pragma unroll
            for (int j = 0; j < 4; j++) b2[j] = pk2(b_f[2*j], b_f[2*j+1]);
            #pragma unroll
            for (int i = 0; i < 8; i++) {
                unsigned long long a2 = pk2(a_f[i], a_f[i]);
                #pragma unroll
                for (int j = 0; j < 4; j++) fma2(acc2[i][j], a2, b2[j]);
            }
        }
        if (knext >= Kd) break;
        __syncthreads();
        #pragma unroll
        for (int jj = 0; jj < 4; jj++) {
            As[a_col + jj][a_row]      = ((const float*)&a_reg[0])[jj];
            As[a_col + jj][a_row + 64] = ((const float*)&a_reg[1])[jj];
        }
        *(float4*)&Bs[b_row][b_col]     = b_reg[0];
        *(float4*)&Bs[b_row + 8][b_col] = b_reg[1];
        __syncthreads();
        k0 = knext;
    }

    float acc[8][8];
    #pragma unroll
    for (int i = 0; i < 8; i++)
        #pragma unroll
        for (int j = 0; j < 4; j++)
            unpk2(acc2[i][j], acc[i][2*j], acc[i][2*j+1]);

    #pragma unroll
    for (int i = 0; i < 8; i++) {
        int row = m0 + ty * 8 + i;
        #pragma unroll
        for (int j = 0; j < 8; j += 4) {
            int col = n0 + tx * 8 + j;
            if (col < N) {
                float4 o;
                o.x = epi_apply<EPI>(acc[i][j + 0], col + 0, vec);
                o.y = epi_apply<EPI>(acc[i][j + 1], col + 1, vec);
                o.z = epi_apply<EPI>(acc[i][j + 2], col + 2, vec);
                o.w = epi_apply<EPI>(acc[i][j + 3], col + 3, vec);
                *(float4*)&C[(size_t)row * ldc + col] = o;
            }
        }
    }
}

// ---------------- fused 5-way token-mix kernel (single-stage, x/dx cached) -----
// smem: t5 tile 64x160 (40KB) + all five B_f 32x128 (80KB) = 120KB, one barrier.
#define MIX_SMEM (64*160*4 + 5*32*128*4)
__global__ void __launch_bounds__(256) mix5_kernel(
    const float* __restrict__ maa_w2,
    const float* __restrict__ x,
    const float* __restrict__ mw, const float* __restrict__ mk,
    const float* __restrict__ mv, const float* __restrict__ mr,
    const float* __restrict__ mg)
{
    extern __shared__ float ms[];
    float* t5s = ms;                 // [64][160]
    float* Bs  = ms + 64 * 160;      // [5][32][128]

    int m0 = blockIdx.y * 64;
    int n0 = blockIdx.x * 128;
    int tid = threadIdx.x;

    // stage t5 tile: 64*40 float4
    for (int i = tid; i < 64 * 40; i += 256) {
        int r = i / 40, c4 = (i % 40) * 4;
        *(float4*)&t5s[r * 160 + c4] = *(const float4*)&g_t5[(size_t)(m0 + r) * 160 + c4];
    }
    // stage all five B tiles: 5*32*32 float4
    for (int i = tid; i < 5 * 32 * 32; i += 256) {
        int f = i / 1024, rem = i % 1024;
        int k = rem / 32, c4 = (rem % 32) * 4;
        *(float4*)&Bs[(f * 32 + k) * 128 + c4] =
            *(const float4*)&maa_w2[((size_t)f * 32 + k) * Dq + n0 + c4];
    }
    __syncthreads();

    int colg = (tid & 31) * 4;
    int row0 = (tid >> 5) * 8;

    // load x/dx once, reuse across all 5 f's
    float4 xv4[8], dxr[8];
    #pragma unroll
    for (int r = 0; r < 8; r++) {
        size_t idx = (size_t)(m0 + row0 + r) * Dq + n0 + colg;
        xv4[r] = *(const float4*)&x[idx];
        dxr[r] = *(const float4*)&g_dx[idx];
    }

    const float* maas[5] = { mw, mk, mv, mr, mg };
    __nv_bfloat16* outH[5] = { nullptr, g_xkh, g_xvh, g_xrh, g_xgh };
    __nv_bfloat16* outL[5] = { nullptr, g_xkl, g_xvl, g_xrl, g_xgl };

    #pragma unroll
    for (int f = 0; f < 5; f++) {
        float acc0[8], acc1[8], acc2_[8], acc3[8];
        #pragma unroll
        for (int r = 0; r < 8; r++) { acc0[r]=0.f; acc1[r]=0.f; acc2_[r]=0.f; acc3[r]=0.f; }

        const float* Bf = &Bs[f * 32 * 128];
        #pragma unroll 4
        for (int k = 0; k < 32; k++) {
            float4 b4 = *(const float4*)&Bf[k * 128 + colg];
            #pragma unroll
            for (int r = 0; r < 8; r++) {
                float a = t5s[(row0 + r) * 160 + f * 32 + k];
                acc0[r] = fmaf(a, b4.x, acc0[r]);
                acc1[r] = fmaf(a, b4.y, acc1[r]);
                acc2_[r] = fmaf(a, b4.z, acc2_[r]);
                acc3[r] = fmaf(a, b4.w, acc3[r]);
            }
        }

        float4 mva = *(const float4*)&maas[f][n0 + colg];
        #pragma unroll
        for (int r = 0; r < 8; r++) {
            size_t idx = (size_t)(m0 + row0 + r) * Dq + n0 + colg;
            float4 o;
            o.x = xv4[r].x + dxr[r].x * (mva.x + acc0[r]);
            o.y = xv4[r].y + dxr[r].y * (mva.y + acc1[r]);
            o.z = xv4[r].z + dxr[r].z * (mva.z + acc2_[r]);
            o.w = xv4[r].w + dxr[r].w * (mva.w + acc3[r]);
            if (f == 0) *(float4*)&g_xw[idx] = o;
            else        store_split4(outH[f], outL[f], idx, o);
        }
    }
}

// ---------------- bidirectional WKV recurrence (64 thr, cp.async, f32x2) -------
__global__ void __launch_bounds__(64) wkv_kernel()
{
    int bh  = blockIdx.x;
    int dir = blockIdx.y;
    int b = bh / Hq, h = bh % Hq;
    size_t base = (size_t)b * Tq * Dq + (size_t)h * Kq;
    int j = threadIdx.x;

    __shared__ __align__(16) float s_r[4][Kq], s_k[4][Kq], s_w[4][Kq], s_v[4][Kq];
    const uint32_t a_r = smem_u32(s_r), a_k = smem_u32(s_k);
    const uint32_t a_w = smem_u32(s_w), a_v = smem_u32(s_v);

    unsigned long long S2[32];
    #pragma unroll
    for (int i = 0; i < 32; i++) S2[i] = 0ull;

    auto issue = [&](int t) {
        int st = t & 3;
        int tr = dir ? (Tq - 1 - t) : t;
        size_t off = base + (size_t)tr * Dq + j;
        uint32_t so = (uint32_t)(st * Kq + j) * 4;
        cp4(a_r + so, &g_r[off]);
        cp4(a_k + so, &g_k[off]);
        cp4(a_w + so, &g_ww[off]);
        cp4(a_v + so, &g_v[off]);
        CP_COMMIT();
    };

    issue(0); issue(1); issue(2);

    for (int t = 0; t < Tq; t++) {
        int st = t & 3;
        CP_WAIT(2);
        __syncthreads();
        if (t + 3 < Tq) issue(t + 3);

        float vj = s_v[st][j];
        unsigned long long v2 = pk2(vj, vj);
        const ulonglong2* r2p = (const ulonglong2*)s_r[st];
        const ulonglong2* k2p = (const ulonglong2*)s_k[st];
        const ulonglong2* w2p = (const ulonglong2*)s_w[st];

        unsigned long long ya = 0ull, yb = 0ull, yc = 0ull, yd = 0ull;

        if (dir == 0) {
            #pragma unroll
            for (int q = 0; q < 16; q += 2) {
                ulonglong2 rq = r2p[q], kq = k2p[q], wq = w2p[q];
                ulonglong2 rq1 = r2p[q+1], kq1 = k2p[q+1], wq1 = w2p[q+1];
                S2[2*q+0] = fma2v(wq.x, S2[2*q+0], mul2(kq.x, v2));
                ya = fma2v(rq.x, S2[2*q+0], ya);
                S2[2*q+1] = fma2v(wq.y, S2[2*q+1], mul2(kq.y, v2));
                yb = fma2v(rq.y, S2[2*q+1], yb);
                S2[2*q+2] = fma2v(wq1.x, S2[2*q+2], mul2(kq1.x, v2));
                yc = fma2v(rq1.x, S2[2*q+2], yc);
                S2[2*q+3] = fma2v(wq1.y, S2[2*q+3], mul2(kq1.y, v2));
                yd = fma2v(rq1.y, S2[2*q+3], yd);
            }
        } else {
            #pragma unroll
            for (int q = 0; q < 16; q += 2) {
                ulonglong2 rq = r2p[q], kq = k2p[q], wq = w2p[q];
                ulonglong2 rq1 = r2p[q+1], kq1 = k2p[q+1], wq1 = w2p[q+1];
                ya = fma2v(rq.x, S2[2*q+0], ya);
                S2[2*q+0] = mul2(wq.x, fma2v(kq.x, v2, S2[2*q+0]));
                yb = fma2v(rq.y, S2[2*q+1], yb);
                S2[2*q+1] = mul2(wq.y, fma2v(kq.y, v2, S2[2*q+1]));
                yc = fma2v(rq1.x, S2[2*q+2], yc);
                S2[2*q+2] = mul2(wq1.x, fma2v(kq1.x, v2, S2[2*q+2]));
                yd = fma2v(rq1.y, S2[2*q+3], yd);
                S2[2*q+3] = mul2(wq1.y, fma2v(kq1.y, v2, S2[2*q+3]));
            }
        }

        float y0, y1, y2, y3, y4, y5, y6, y7;
        unpk2(ya, y0, y1); unpk2(yb, y2, y3);
        unpk2(yc, y4, y5); unpk2(yd, y6, y7);
        float y = ((y0 + y1) + (y2 + y3)) + ((y4 + y5) + (y6 + y7));

        int tr = dir ? (Tq - 1 - t) : t;
        size_t off = base + (size_t)tr * Dq + j;
        if (dir == 0) g_yf[off] = y;
        else          g_yb[off] = y;
    }
}

// ---------------- groupnorm + output gate + silu-gate (→ z hi/lo) ---------------
__global__ void __launch_bounds__(128) gn_kernel(const float* __restrict__ ln_w,
                                                 const float* __restrict__ ln_b)
{
    int gidx = blockIdx.x * 4 + (threadIdx.x >> 5);
    int lane = threadIdx.x & 31;
    int bt = gidx / Hq, h = gidx % Hq;
    size_t rowbase = (size_t)bt * Dq + (size_t)h * Kq;
    size_t i0 = rowbase + lane, i1 = rowbase + lane + 32;

    float a = (g_yf[i0] + g_yb[i0]) * g_gate[i0];
    float c = (g_yf[i1] + g_yb[i1]) * g_gate[i1];
    float s = a + c, sq = a * a + c * c;
    #pragma unroll
    for (int o = 16; o; o >>= 1) {
        s  += __shfl_xor_sync(0xffffffffu, s,  o);
        sq += __shfl_xor_sync(0xffffffffu, sq, o);
    }
    float mean = s * (1.f / 64.f);
    float var  = sq * (1.f / 64.f) - mean * mean;
    float rstd = rsqrtf(var + 6.4e-4f);
    int d0 = h * Kq + lane, d1 = d0 + 32;
    float z0 = ((a - mean) * rstd * ln_w[d0] + ln_b[d0]) * g_g[i0];
    float z1 = ((c - mean) * rstd * ln_w[d1] + ln_b[d1]) * g_g[i1];
    __nv_bfloat16 h0 = __float2bfloat16(z0);
    __nv_bfloat16 h1 = __float2bfloat16(z1);
    g_zh[i0] = h0; g_zl[i0] = __float2bfloat16(z0 - __bfloat162float(h0));
    g_zh[i1] = h1; g_zl[i1] = __float2bfloat16(z1 - __bfloat162float(h1));
}

// ---------------- launch --------------------------------------------------------
extern "C" void kernel_launch(void* const* d_in, const int* in_sizes, int n_in,
                              void* d_out, int out_size)
{
    const float* x          = (const float*)d_in[0];
    const float* conv_w     = (const float*)d_in[1];
    const float* maa_x      = (const float*)d_in[2];
    const float* maa_w      = (const float*)d_in[3];
    const float* maa_k      = (const float*)d_in[4];
    const float* maa_v      = (const float*)d_in[5];
    const float* maa_r      = (const float*)d_in[6];
    const float* maa_g      = (const float*)d_in[7];
    const float* maa_w1     = (const float*)d_in[8];
    const float* maa_w2     = (const float*)d_in[9];
    const float* time_decay = (const float*)d_in[10];
    const float* decay_w1   = (const float*)d_in[11];
    const float* decay_w2   = (const float*)d_in[12];
    const float* Wr         = (const float*)d_in[13];
    const float* Wk         = (const float*)d_in[14];
    const float* Wv         = (const float*)d_in[15];
    const float* Wg         = (const float*)d_in[16];
    const float* Wo         = (const float*)d_in[17];
    const float* ln_w       = (const float*)d_in[18];
    const float* ln_b       = (const float*)d_in[19];
    const float* gate_w     = (const float*)d_in[20];
    const float* gate_b     = (const float*)d_in[21];
    float* out = (float*)d_out;

    float *p_t5, *p_xw, *p_r, *p_k, *p_v, *p_g, *p_h, *p_ww, *p_gate;
    __nv_bfloat16 *p_xxh, *p_xxl, *p_dxh, *p_dxl, *p_xkh, *p_xkl, *p_xvh, *p_xvl;
    __nv_bfloat16 *p_xrh, *p_xrl, *p_xgh, *p_xgl, *p_zh, *p_zl, *p_wh, *p_wl;
    __nv_bfloat16 *p_w1h, *p_w1l;
    cudaGetSymbolAddress((void**)&p_t5,   g_t5);
    cudaGetSymbolAddress((void**)&p_xw,   g_xw);
    cudaGetSymbolAddress((void**)&p_r,    g_r);
    cudaGetSymbolAddress((void**)&p_k,    g_k);
    cudaGetSymbolAddress((void**)&p_v,    g_v);
    cudaGetSymbolAddress((void**)&p_g,    g_g);
    cudaGetSymbolAddress((void**)&p_h,    g_hbuf);
    cudaGetSymbolAddress((void**)&p_ww,   g_ww);
    cudaGetSymbolAddress((void**)&p_gate, g_gate);
    cudaGetSymbolAddress((void**)&p_xxh,  g_xxh);
    cudaGetSymbolAddress((void**)&p_xxl,  g_xxl);
    cudaGetSymbolAddress((void**)&p_dxh,  g_dxh);
    cudaGetSymbolAddress((void**)&p_dxl,  g_dxl);
    cudaGetSymbolAddress((void**)&p_xkh,  g_xkh);
    cudaGetSymbolAddress((void**)&p_xkl,  g_xkl);
    cudaGetSymbolAddress((void**)&p_xvh,  g_xvh);
    cudaGetSymbolAddress((void**)&p_xvl,  g_xvl);
    cudaGetSymbolAddress((void**)&p_xrh,  g_xrh);
    cudaGetSymbolAddress((void**)&p_xrl,  g_xrl);
    cudaGetSymbolAddress((void**)&p_xgh,  g_xgh);
    cudaGetSymbolAddress((void**)&p_xgl,  g_xgl);
    cudaGetSymbolAddress((void**)&p_zh,   g_zh);
    cudaGetSymbolAddress((void**)&p_zl,   g_zl);
    cudaGetSymbolAddress((void**)&p_wh,   g_wh);
    cudaGetSymbolAddress((void**)&p_wl,   g_wl);
    cudaGetSymbolAddress((void**)&p_w1h,  g_w1h);
    cudaGetSymbolAddress((void**)&p_w1l,  g_w1l);

    cudaFuncSetAttribute((const void*)hmma_gemm<TEPI_NONE,3>, cudaFuncAttributeMaxDynamicSharedMemorySize, HM_SMEM);
    cudaFuncSetAttribute((const void*)hmma_gemm<TEPI_SILU,3>, cudaFuncAttributeMaxDynamicSharedMemorySize, HM_SMEM);
    cudaFuncSetAttribute((const void*)hmma_gemm<TEPI_GATE,3>, cudaFuncAttributeMaxDynamicSharedMemorySize, HM_SMEM);
    cudaFuncSetAttribute((const void*)hmma_gemm<TEPI_TANH,4>, cudaFuncAttributeMaxDynamicSharedMemorySize, HM_SMEM);
    cudaFuncSetAttribute((const void*)mix5_kernel, cudaFuncAttributeMaxDynamicSharedMemorySize, MIX_SMEM);

    // 0) conv / dx fp32+hi/lo / xxx hi/lo
    {
        int threads = 256;
        int blocks  = (int)((BTDq + threads - 1) / threads);
        conv_kernel<<<blocks, threads>>>(x, conv_w, maa_x);
    }

    // 1) weight transpose + split
    {
        dim3 g(32, 32, 6);
        wsplit_kernel<<<g, 256>>>(Wr, Wk, Wv, Wg, gate_w, Wo);
    }
    // 2) maa_w1 transpose + split
    {
        dim3 g(5, 32);
        wsplit_w1_kernel<<<g, 256>>>(maa_w1);
    }

    dim3 blk(256);
    dim3 grid_64(1, Mq / BMt);
    dim3 grid_dec(Dq / BNt, Mq / BMt);
    dim3 hm_grid(8, Mq / 128);
    dim3 hm_t5(2, Mq / 128);

    // 3) t5 = tanh(xxx @ maa_w1)  [HMMA 4-pass, N=160]
    hmma_gemm<TEPI_TANH,4><<<hm_t5, 256, HM_SMEM>>>(p_xxh, p_xxl, p_w1h, p_w1l,
                                                    p_t5, nullptr, 160, 160);

    // 4) fused token-mix (single-stage, x/dx cached in registers)
    {
        dim3 g(Dq / 128, Mq / 64);
        mix5_kernel<<<g, 256, MIX_SMEM>>>(maa_w2, x, maa_w, maa_k, maa_v, maa_r, maa_g);
    }

    const size_t WS = 1024 * 1024;
    // 5) big projections (3-pass; fp32 dx is the accuracy anchor per R4)
    hmma_gemm<TEPI_NONE,3><<<hm_grid, 256, HM_SMEM>>>(p_xrh, p_xrl, p_wh + 0*WS, p_wl + 0*WS, p_r, nullptr, 1024, 1024);
    hmma_gemm<TEPI_NONE,3><<<hm_grid, 256, HM_SMEM>>>(p_xkh, p_xkl, p_wh + 1*WS, p_wl + 1*WS, p_k, nullptr, 1024, 1024);
    hmma_gemm<TEPI_NONE,3><<<hm_grid, 256, HM_SMEM>>>(p_xvh, p_xvl, p_wh + 2*WS, p_wl + 2*WS, p_v, nullptr, 1024, 1024);
    hmma_gemm<TEPI_SILU,3><<<hm_grid, 256, HM_SMEM>>>(p_xgh, p_xgl, p_wh + 3*WS, p_wl + 3*WS, p_g, nullptr, 1024, 1024);
    hmma_gemm<TEPI_GATE,3><<<hm_grid, 256, HM_SMEM>>>(p_dxh, p_dxl, p_wh + 4*WS, p_wl + 4*WS, p_gate, gate_b, 1024, 1024);

    // 6) decay MLP (scalar fp32 for precision)
    sgemm<EPI_TANH><<<grid_64, blk>>>(p_xw, Dq, decay_w1, 64, p_h, 64,
                                      64, Dq, nullptr);
    sgemm<EPI_DECAY><<<grid_dec, blk>>>(p_h, 64, decay_w2, Dq, p_ww, Dq,
                                        Dq, 64, time_decay);

    // 7) bidirectional recurrence
    {
        dim3 g(Bq * Hq, 2);
        wkv_kernel<<<g, 64>>>();
    }

    // 8) gate + groupnorm + silu-gate → z hi/lo
    gn_kernel<<<(Mq * Hq) / 4, 128>>>(ln_w, ln_b);

    // 9) out = z @ Wo (HMMA 3-pass)
    hmma_gemm<TEPI_NONE,3><<<hm_grid, 256, HM_SMEM>>>(p_zh, p_zl, p_wh + 5*WS, p_wl + 5*WS, out, nullptr, 1024, 1024);
}

// round 14
// speedup vs baseline: 1.5864x; 1.5864x over previous
#include <cuda_runtime.h>
#include <cuda_bf16.h>
#include <math.h>
#include <stdint.h>

// Problem constants
#define Bq 8
#define Tq 2048
#define Dq 1024
#define Hq 16
#define Kq 64
#define Mq (Bq*Tq)                 // 16384 rows
#define BTDq ((size_t)Mq*(size_t)Dq)

// ---------------- scratch (device globals; no allocations allowed) -------------
__device__ float g_dx  [Mq*Dq];
__device__ float g_t5  [Mq*160];
__device__ float g_xw  [Mq*Dq];
__device__ float g_r   [Mq*Dq];
__device__ float g_k   [Mq*Dq];
__device__ float g_v   [Mq*Dq];
__device__ float g_g   [Mq*Dq];
__device__ float g_hbuf[Mq*64];
__device__ float g_ww  [Mq*Dq];
__device__ float g_gate[Mq*Dq];
__device__ float g_yf  [Mq*Dq];
__device__ float g_yb  [Mq*Dq];

// bf16 hi/lo split activations
__device__ __nv_bfloat16 g_xxh[Mq*Dq], g_xxl[Mq*Dq];
__device__ __nv_bfloat16 g_dxh[Mq*Dq], g_dxl[Mq*Dq];
__device__ __nv_bfloat16 g_xkh[Mq*Dq], g_xkl[Mq*Dq];
__device__ __nv_bfloat16 g_xvh[Mq*Dq], g_xvl[Mq*Dq];
__device__ __nv_bfloat16 g_xrh[Mq*Dq], g_xrl[Mq*Dq];
__device__ __nv_bfloat16 g_xgh[Mq*Dq], g_xgl[Mq*Dq];
__device__ __nv_bfloat16 g_zh [Mq*Dq], g_zl [Mq*Dq];
// transposed weights [N,K] hi/lo, 6 slots: Wr,Wk,Wv,Wg,gate_w,Wo
__device__ __nv_bfloat16 g_wh[6*1024*1024], g_wl[6*1024*1024];
// maa_w1 transposed [160(+pad to 256),1024] hi/lo
__device__ __nv_bfloat16 g_w1h[256*1024], g_w1l[256*1024];

// ---------------- helpers -------------------------------------------------------
__device__ __forceinline__ uint32_t smem_u32(const void* p) {
    uint32_t a;
    asm("{ .reg .u64 t; cvta.to.shared.u64 t, %1; cvt.u32.u64 %0, t; }" : "=r"(a) : "l"(p));
    return a;
}
__device__ __forceinline__ void cp16(uint32_t dst, const void* src) {
    asm volatile("cp.async.cg.shared.global [%0], [%1], 16;" :: "r"(dst), "l"(src));
}
__device__ __forceinline__ void cp4(uint32_t dst, const void* src) {
    asm volatile("cp.async.ca.shared.global [%0], [%1], 4;" :: "r"(dst), "l"(src));
}
#define CP_COMMIT() asm volatile("cp.async.commit_group;" ::: "memory")
#define CP_WAIT(n)  asm volatile("cp.async.wait_group %0;" :: "n"(n) : "memory")

#define LDSM4(R0, R1, R2, R3, ADDR) \
    asm volatile("ldmatrix.sync.aligned.m8n8.x4.shared.b16 {%0,%1,%2,%3}, [%4];" \
        : "=r"(R0), "=r"(R1), "=r"(R2), "=r"(R3) : "r"(ADDR))

#define MMA_BF16(D, A, B0, B1) \
    asm volatile("mma.sync.aligned.m16n8k16.row.col.f32.bf16.bf16.f32 " \
        "{%0,%1,%2,%3}, {%4,%5,%6,%7}, {%8,%9}, {%0,%1,%2,%3};" \
        : "+f"((D)[0]), "+f"((D)[1]), "+f"((D)[2]), "+f"((D)[3]) \
        : "r"((A)[0]), "r"((A)[1]), "r"((A)[2]), "r"((A)[3]), "r"(B0), "r"(B1))

// packed f32x2 helpers
__device__ __forceinline__ unsigned long long pk2(float lo, float hi) {
    unsigned long long r;
    asm("mov.b64 %0, {%1, %2};" : "=l"(r) : "f"(lo), "f"(hi));
    return r;
}
__device__ __forceinline__ void fma2(unsigned long long& d,
                                     unsigned long long a,
                                     unsigned long long b) {
    asm("fma.rn.f32x2 %0, %1, %2, %0;" : "+l"(d) : "l"(a), "l"(b));
}
__device__ __forceinline__ unsigned long long fma2v(unsigned long long a,
                                                    unsigned long long b,
                                                    unsigned long long c) {
    unsigned long long d;
    asm("fma.rn.f32x2 %0, %1, %2, %3;" : "=l"(d) : "l"(a), "l"(b), "l"(c));
    return d;
}
__device__ __forceinline__ unsigned long long mul2(unsigned long long a,
                                                   unsigned long long b) {
    unsigned long long d;
    asm("mul.rn.f32x2 %0, %1, %2;" : "=l"(d) : "l"(a), "l"(b));
    return d;
}
__device__ __forceinline__ void unpk2(unsigned long long v, float& lo, float& hi) {
    asm("mov.b64 {%0, %1}, %2;" : "=f"(lo), "=f"(hi) : "l"(v));
}

// hi/lo split store of 4 consecutive floats
__device__ __forceinline__ void store_split4(__nv_bfloat16* H, __nv_bfloat16* L,
                                             size_t idx, float4 o) {
    __nv_bfloat162 h01 = __floats2bfloat162_rn(o.x, o.y);
    __nv_bfloat162 h23 = __floats2bfloat162_rn(o.z, o.w);
    float2 f01 = __bfloat1622float2(h01);
    float2 f23 = __bfloat1622float2(h23);
    __nv_bfloat162 l01 = __floats2bfloat162_rn(o.x - f01.x, o.y - f01.y);
    __nv_bfloat162 l23 = __floats2bfloat162_rn(o.z - f23.x, o.w - f23.y);
    uint2 hv = make_uint2(*(unsigned*)&h01, *(unsigned*)&h23);
    uint2 lv = make_uint2(*(unsigned*)&l01, *(unsigned*)&l23);
    *(uint2*)&H[idx] = hv;
    *(uint2*)&L[idx] = lv;
}

// ---------------- kernel: depthwise conv (k=3), dx fp32+hi/lo, xxx hi/lo -------
__global__ void conv_kernel(const float* __restrict__ x,
                            const float* __restrict__ cw,
                            const float* __restrict__ maa_x)
{
    size_t idx = (size_t)blockIdx.x * blockDim.x + threadIdx.x;
    if (idx >= BTDq) return;
    int d = (int)(idx & (Dq - 1));
    int t = (int)((idx / Dq) & (Tq - 1));
    float x0 = x[idx];
    float xm = (t > 0)      ? x[idx - Dq] : 0.f;
    float xp = (t < Tq - 1) ? x[idx + Dq] : 0.f;
    float dxv = cw[d*3+0]*xm + cw[d*3+1]*x0 + cw[d*3+2]*xp - x0;
    float xxx = x0 + dxv * maa_x[d];
    g_dx[idx] = dxv;
    __nv_bfloat16 h = __float2bfloat16(dxv);
    g_dxh[idx] = h;
    g_dxl[idx] = __float2bfloat16(dxv - __bfloat162float(h));
    __nv_bfloat16 xh = __float2bfloat16(xxx);
    g_xxh[idx] = xh;
    g_xxl[idx] = __float2bfloat16(xxx - __bfloat162float(xh));
}

// ---------------- kernel: weight transpose + bf16 split (6 slots) --------------
__global__ void __launch_bounds__(256) wsplit_kernel(
    const float* __restrict__ W0, const float* __restrict__ W1,
    const float* __restrict__ W2, const float* __restrict__ W3,
    const float* __restrict__ W4, const float* __restrict__ W5)
{
    __shared__ float tile[32][33];
    const float* Ws[6] = { W0, W1, W2, W3, W4, W5 };
    const float* W = Ws[blockIdx.z];
    __nv_bfloat16* H = g_wh + (size_t)blockIdx.z * 1024 * 1024;
    __nv_bfloat16* L = g_wl + (size_t)blockIdx.z * 1024 * 1024;
    int n0 = blockIdx.x * 32, k0 = blockIdx.y * 32;
    int tx = threadIdx.x & 31, ty = threadIdx.x >> 5;
    #pragma unroll
    for (int i = 0; i < 4; i++)
        tile[ty + i*8][tx] = W[(size_t)(k0 + ty + i*8) * 1024 + n0 + tx];
    __syncthreads();
    #pragma unroll
    for (int i = 0; i < 4; i++) {
        float v = tile[tx][ty + i*8];
        __nv_bfloat16 h = __float2bfloat16(v);
        size_t o = (size_t)(n0 + ty + i*8) * 1024 + k0 + tx;
        H[o] = h;
        L[o] = __float2bfloat16(v - __bfloat162float(h));
    }
}

// ---------------- kernel: maa_w1 [1024,160] -> [160,1024] hi/lo ----------------
__global__ void __launch_bounds__(256) wsplit_w1_kernel(const float* __restrict__ W1)
{
    __shared__ float tile[32][33];
    int n0 = blockIdx.x * 32, k0 = blockIdx.y * 32;   // n<160, k<1024
    int tx = threadIdx.x & 31, ty = threadIdx.x >> 5;
    #pragma unroll
    for (int i = 0; i < 4; i++)
        tile[ty + i*8][tx] = W1[(size_t)(k0 + ty + i*8) * 160 + n0 + tx];
    __syncthreads();
    #pragma unroll
    for (int i = 0; i < 4; i++) {
        float v = tile[tx][ty + i*8];
        __nv_bfloat16 h = __float2bfloat16(v);
        size_t o = (size_t)(n0 + ty + i*8) * 1024 + k0 + tx;
        g_w1h[o] = h;
        g_w1l[o] = __float2bfloat16(v - __bfloat162float(h));
    }
}

// ---------------- HMMA bf16 split GEMM (mma.sync), 3-stage pipeline ------------
// PASSES=3: AhBh + AhBl + AlBh.  PASSES=4: + AlBl
#define HM_SMEM 98304
enum { TEPI_NONE = 0, TEPI_SILU, TEPI_GATE, TEPI_TANH };

template<int EPI>
__device__ __forceinline__ float tepi(float a, int col, const float* __restrict__ vec) {
    if (EPI == TEPI_SILU) return a / (1.f + __expf(-a));
    if (EPI == TEPI_GATE) return 1.f / (1.f + __expf(-(a + vec[col])));
    if (EPI == TEPI_TANH) return tanhf(a);
    return a;
}

template<int EPI, int PASSES>
__global__ void __launch_bounds__(256, 1) hmma_gemm(
    const __nv_bfloat16* __restrict__ Ah, const __nv_bfloat16* __restrict__ Al,
    const __nv_bfloat16* __restrict__ Bh, const __nv_bfloat16* __restrict__ Bl,
    float* __restrict__ C, const float* __restrict__ vec,
    int N, int ldc)
{
    extern __shared__ __align__(128) char sm[];
    const uint32_t sb = smem_u32(sm);
    const int tid = threadIdx.x, lane = tid & 31, wid = tid >> 5;
    const int m0 = blockIdx.y * 128, n0 = blockIdx.x * 128;
    const int wm = (wid & 1) * 64;
    const int wn = (wid >> 1) * 32;

    const int ldrow = (tid >> 2);
    const int ldk16 = tid & 3;

    float acc[4][4][4];
    #pragma unroll
    for (int a = 0; a < 4; a++)
        #pragma unroll
        for (int b = 0; b < 4; b++)
            #pragma unroll
            for (int c = 0; c < 4; c++) acc[a][b][c] = 0.f;

    auto load_chunk = [&](int c) {
        const uint32_t base = sb + (uint32_t)(c % 3) * 32768;
        const int kc = c * 32;
        #pragma unroll
        for (int h = 0; h < 2; h++) {
            int row = ldrow + h * 64;
            uint32_t sw = (uint32_t)row * 64 + (uint32_t)((ldk16 ^ ((row >> 1) & 3)) << 4);
            size_t ga = (size_t)(m0 + row) * 1024 + kc + ldk16 * 8;
            size_t gb = (size_t)(n0 + row) * 1024 + kc + ldk16 * 8;
            cp16(base +         sw, Ah + ga);
            cp16(base +  8192 + sw, Al + ga);
            cp16(base + 16384 + sw, Bh + gb);
            cp16(base + 24576 + sw, Bl + gb);
        }
        CP_COMMIT();
    };

    load_chunk(0);
    load_chunk(1);

    const int rowl = lane & 15;
    const int s3 = (rowl >> 1) & 3;
    const int chnk = lane >> 4;

    for (int c = 0; c < 32; c++) {
        CP_WAIT(1);
        __syncthreads();
        if (c + 2 < 32) load_chunk(c + 2);

        const uint32_t st = sb + (uint32_t)(c % 3) * 32768;
        const uint32_t aBase = st + (uint32_t)(wm + rowl) * 64;
        const uint32_t bBase = st + 16384 + (uint32_t)(wn + rowl) * 64;

        #pragma unroll
        for (int ks = 0; ks < 2; ks++) {
            const uint32_t sw = (uint32_t)(((2 * ks + chnk) ^ s3) << 4);
            uint32_t ah[4][4], al[4][4], bh[2][4], bl[2][4];
            #pragma unroll
            for (int mi = 0; mi < 4; mi++) {
                LDSM4(ah[mi][0], ah[mi][1], ah[mi][2], ah[mi][3], aBase + mi * 1024 + sw);
                LDSM4(al[mi][0], al[mi][1], al[mi][2], al[mi][3], aBase + 8192 + mi * 1024 + sw);
            }
            #pragma unroll
            for (int nf = 0; nf < 2; nf++) {
                LDSM4(bh[nf][0], bh[nf][1], bh[nf][2], bh[nf][3], bBase + nf * 1024 + sw);
                LDSM4(bl[nf][0], bl[nf][1], bl[nf][2], bl[nf][3], bBase + 8192 + nf * 1024 + sw);
            }
            #pragma unroll
            for (int mi = 0; mi < 4; mi++) {
                #pragma unroll
                for (int nj = 0; nj < 4; nj++) {
                    uint32_t b0h = bh[nj >> 1][nj & 1], b1h = bh[nj >> 1][(nj & 1) + 2];
                    uint32_t b0l = bl[nj >> 1][nj & 1], b1l = bl[nj >> 1][(nj & 1) + 2];
                    MMA_BF16(acc[mi][nj], ah[mi], b0h, b1h);
                    MMA_BF16(acc[mi][nj], ah[mi], b0l, b1l);
                    MMA_BF16(acc[mi][nj], al[mi], b0h, b1h);
                    if (PASSES == 4) MMA_BF16(acc[mi][nj], al[mi], b0l, b1l);
                }
            }
        }
    }

    const int er = lane >> 2, ec = (lane & 3) * 2;
    #pragma unroll
    for (int mi = 0; mi < 4; mi++) {
        #pragma unroll
        for (int nj = 0; nj < 4; nj++) {
            int row = m0 + wm + mi * 16 + er;
            int col = n0 + wn + nj * 8 + ec;
            if (col < N) {
                float2 o0, o1;
                o0.x = tepi<EPI>(acc[mi][nj][0], col,     vec);
                o0.y = tepi<EPI>(acc[mi][nj][1], col + 1, vec);
                o1.x = tepi<EPI>(acc[mi][nj][2], col,     vec);
                o1.y = tepi<EPI>(acc[mi][nj][3], col + 1, vec);
                *(float2*)&C[(size_t)row * ldc + col]       = o0;
                *(float2*)&C[(size_t)(row + 8) * ldc + col] = o1;
            }
        }
    }
}

// ---------------- scalar SGEMM (FFMA2) for decay GEMMs (fp32 precision) --------
#define BMt 128
#define BNt 128
#define BKt 16
enum { EPI_NONE = 0, EPI_TANH, EPI_DECAY };

template<int EPI>
__device__ __forceinline__ float epi_apply(float acc, int col,
                                           const float* __restrict__ vec)
{
    if (EPI == EPI_TANH)  return tanhf(acc);
    if (EPI == EPI_DECAY) return __expf(-__expf(vec[col] + acc));
    return acc;
}

template<int EPI>
__global__ void __launch_bounds__(256, 2) sgemm(
    const float* __restrict__ A, int lda,
    const float* __restrict__ Bm, int ldb,
    float* __restrict__ C, int ldc,
    int N, int Kd,
    const float* __restrict__ vec)
{
    __shared__ float As[BKt][BMt];
    __shared__ float Bs[BKt][BNt];

    int tid = threadIdx.x;
    int m0  = blockIdx.y * BMt;
    int n0  = blockIdx.x * BNt;

    int a_row = tid >> 2;
    int a_col = (tid & 3) << 2;
    int b_row = tid >> 5;
    int b_col = (tid & 31) << 2;
    int ty = tid >> 4, tx = tid & 15;

    const float* Aptr = A + (size_t)m0 * lda;
    bool bvalid = (n0 + b_col) < N;
    const float4 z4 = make_float4(0.f, 0.f, 0.f, 0.f);

    float4 a_reg[2], b_reg[2];
    a_reg[0] = *(const float4*)(Aptr + (size_t)a_row       * lda + a_col);
    a_reg[1] = *(const float4*)(Aptr + (size_t)(a_row + 64) * lda + a_col);
    b_reg[0] = bvalid ? *(const float4*)(Bm + (size_t)b_row       * ldb + n0 + b_col) : z4;
    b_reg[1] = bvalid ? *(const float4*)(Bm + (size_t)(b_row + 8) * ldb + n0 + b_col) : z4;

    #pragma unroll
    for (int jj = 0; jj < 4; jj++) {
        As[a_col + jj][a_row]      = ((const float*)&a_reg[0])[jj];
        As[a_col + jj][a_row + 64] = ((const float*)&a_reg[1])[jj];
    }
    *(float4*)&Bs[b_row][b_col]     = b_reg[0];
    *(float4*)&Bs[b_row + 8][b_col] = b_reg[1];
    __syncthreads();

    unsigned long long acc2[8][4];
    #pragma unroll
    for (int i = 0; i < 8; i++)
        #pragma unroll
        for (int j = 0; j < 4; j++)
            acc2[i][j] = 0ull;

    for (int k0 = 0;;) {
        int knext = k0 + BKt;
        if (knext < Kd) {
            a_reg[0] = *(const float4*)(Aptr + (size_t)a_row       * lda + knext + a_col);
            a_reg[1] = *(const float4*)(Aptr + (size_t)(a_row + 64) * lda + knext + a_col);
            b_reg[0] = bvalid ? *(const float4*)(Bm + (size_t)(knext + b_row)     * ldb + n0 + b_col) : z4;
            b_reg[1] = bvalid ? *(const float4*)(Bm + (size_t)(knext + b_row + 8) * ldb + n0 + b_col) : z4;
        }
        #pragma unroll
        for (int kk = 0; kk < BKt; kk++) {
            float a_f[8], b_f[8];
            *(float4*)&a_f[0] = *(const float4*)&As[kk][ty * 8];
            *(float4*)&a_f[4] = *(const float4*)&As[kk][ty * 8 + 4];
            *(float4*)&b_f[0] = *(const float4*)&Bs[kk][tx * 8];
            *(float4*)&b_f[4] = *(const float4*)&Bs[kk][tx * 8 + 4];
            unsigned long long b2[4];
            #pragma unroll
            for (int j = 0; j < 4; j++) b2[j] = pk2(b_f[2*j], b_f[2*j+1]);
            #pragma unroll
            for (int i = 0; i < 8; i++) {
                unsigned long long a2 = pk2(a_f[i], a_f[i]);
                #pragma unroll
                for (int j = 0; j < 4; j++) fma2(acc2[i][j], a2, b2[j]);
            }
        }
        if (knext >= Kd) break;
        __syncthreads();
        #pragma unroll
        for (int jj = 0; jj < 4; jj++) {
            As[a_col + jj][a_row]      = ((const float*)&a_reg[0])[jj];
            As[a_col + jj][a_row + 64] = ((const float*)&a_reg[1])[jj];
        }
        *(float4*)&Bs[b_row][b_col]     = b_reg[0];
        *(float4*)&Bs[b_row + 8][b_col] = b_reg[1];
        __syncthreads();
        k0 = knext;
    }

    float acc[8][8];
    #pragma unroll
    for (int i = 0; i < 8; i++)
        #pragma unroll
        for (int j = 0; j < 4; j++)
            unpk2(acc2[i][j], acc[i][2*j], acc[i][2*j+1]);

    #pragma unroll
    for (int i = 0; i < 8; i++) {
        int row = m0 + ty * 8 + i;
        #pragma unroll
        for (int j = 0; j < 8; j += 4) {
            int col = n0 + tx * 8 + j;
            if (col < N) {
                float4 o;
                o.x = epi_apply<EPI>(acc[i][j + 0], col + 0, vec);
                o.y = epi_apply<EPI>(acc[i][j + 1], col + 1, vec);
                o.z = epi_apply<EPI>(acc[i][j + 2], col + 2, vec);
                o.w = epi_apply<EPI>(acc[i][j + 3], col + 3, vec);
                *(float4*)&C[(size_t)row * ldc + col] = o;
            }
        }
    }
}

// ---------------- fused 5-way token-mix kernel (fp32 dx, R10 form) --------------
__global__ void __launch_bounds__(256) mix5_kernel(
    const float* __restrict__ maa_w2,
    const float* __restrict__ x,
    const float* __restrict__ mw, const float* __restrict__ mk,
    const float* __restrict__ mv, const float* __restrict__ mr,
    const float* __restrict__ mg)
{
    __shared__ float t5s[64][160];
    __shared__ float Bs[32][128];

    int m0 = blockIdx.y * 64;
    int n0 = blockIdx.x * 128;
    int tid = threadIdx.x;

    for (int i = tid; i < 64 * 40; i += 256) {
        int r = i / 40, c4 = (i % 40) * 4;
        *(float4*)&t5s[r][c4] = *(const float4*)&g_t5[(size_t)(m0 + r) * 160 + c4];
    }

    int colg = (tid & 31) * 4;
    int row0 = (tid >> 5) * 8;

    const float* maas[5] = { mw, mk, mv, mr, mg };
    __nv_bfloat16* outH[5] = { nullptr, g_xkh, g_xvh, g_xrh, g_xgh };
    __nv_bfloat16* outL[5] = { nullptr, g_xkl, g_xvl, g_xrl, g_xgl };

    #pragma unroll
    for (int f = 0; f < 5; f++) {
        __syncthreads();
        for (int i = tid; i < 32 * 32; i += 256) {
            int k = i / 32, c4 = (i % 32) * 4;
            *(float4*)&Bs[k][c4] =
                *(const float4*)&maa_w2[((size_t)f * 32 + k) * Dq + n0 + c4];
        }
        __syncthreads();

        float acc0[8], acc1[8], acc2_[8], acc3[8];
        #pragma unroll
        for (int r = 0; r < 8; r++) { acc0[r]=0.f; acc1[r]=0.f; acc2_[r]=0.f; acc3[r]=0.f; }

        #pragma unroll 4
        for (int k = 0; k < 32; k++) {
            float4 b4 = *(const float4*)&Bs[k][colg];
            #pragma unroll
            for (int r = 0; r < 8; r++) {
                float a = t5s[row0 + r][f * 32 + k];
                acc0[r] = fmaf(a, b4.x, acc0[r]);
                acc1[r] = fmaf(a, b4.y, acc1[r]);
                acc2_[r] = fmaf(a, b4.z, acc2_[r]);
                acc3[r] = fmaf(a, b4.w, acc3[r]);
            }
        }

        float4 mva = *(const float4*)&maas[f][n0 + colg];
        #pragma unroll
        for (int r = 0; r < 8; r++) {
            size_t idx = (size_t)(m0 + row0 + r) * Dq + n0 + colg;
            float4 xv4 = *(const float4*)&x[idx];
            float4 dx4 = *(const float4*)&g_dx[idx];
            float4 o;
            o.x = xv4.x + dx4.x * (mva.x + acc0[r]);
            o.y = xv4.y + dx4.y * (mva.y + acc1[r]);
            o.z = xv4.z + dx4.z * (mva.z + acc2_[r]);
            o.w = xv4.w + dx4.w * (mva.w + acc3[r]);
            if (f == 0) *(float4*)&g_xw[idx] = o;
            else        store_split4(outH[f], outL[f], idx, o);
        }
    }
}

// ---------------- bidirectional WKV recurrence (64 thr, cp.async, f32x2) -------
__global__ void __launch_bounds__(64) wkv_kernel()
{
    int bh  = blockIdx.x;
    int dir = blockIdx.y;
    int b = bh / Hq, h = bh % Hq;
    size_t base = (size_t)b * Tq * Dq + (size_t)h * Kq;
    int j = threadIdx.x;

    __shared__ __align__(16) float s_r[4][Kq], s_k[4][Kq], s_w[4][Kq], s_v[4][Kq];
    const uint32_t a_r = smem_u32(s_r), a_k = smem_u32(s_k);
    const uint32_t a_w = smem_u32(s_w), a_v = smem_u32(s_v);

    unsigned long long S2[32];
    #pragma unroll
    for (int i = 0; i < 32; i++) S2[i] = 0ull;

    auto issue = [&](int t) {
        int st = t & 3;
        int tr = dir ? (Tq - 1 - t) : t;
        size_t off = base + (size_t)tr * Dq + j;
        uint32_t so = (uint32_t)(st * Kq + j) * 4;
        cp4(a_r + so, &g_r[off]);
        cp4(a_k + so, &g_k[off]);
        cp4(a_w + so, &g_ww[off]);
        cp4(a_v + so, &g_v[off]);
        CP_COMMIT();
    };

    issue(0); issue(1); issue(2);

    for (int t = 0; t < Tq; t++) {
        int st = t & 3;
        CP_WAIT(2);
        __syncthreads();
        if (t + 3 < Tq) issue(t + 3);

        float vj = s_v[st][j];
        unsigned long long v2 = pk2(vj, vj);
        const ulonglong2* r2p = (const ulonglong2*)s_r[st];
        const ulonglong2* k2p = (const ulonglong2*)s_k[st];
        const ulonglong2* w2p = (const ulonglong2*)s_w[st];

        unsigned long long ya = 0ull, yb = 0ull, yc = 0ull, yd = 0ull;

        if (dir == 0) {
            #pragma unroll
            for (int q = 0; q < 16; q += 2) {
                ulonglong2 rq = r2p[q], kq = k2p[q], wq = w2p[q];
                ulonglong2 rq1 = r2p[q+1], kq1 = k2p[q+1], wq1 = w2p[q+1];
                S2[2*q+0] = fma2v(wq.x, S2[2*q+0], mul2(kq.x, v2));
                ya = fma2v(rq.x, S2[2*q+0], ya);
                S2[2*q+1] = fma2v(wq.y, S2[2*q+1], mul2(kq.y, v2));
                yb = fma2v(rq.y, S2[2*q+1], yb);
                S2[2*q+2] = fma2v(wq1.x, S2[2*q+2], mul2(kq1.x, v2));
                yc = fma2v(rq1.x, S2[2*q+2], yc);
                S2[2*q+3] = fma2v(wq1.y, S2[2*q+3], mul2(kq1.y, v2));
                yd = fma2v(rq1.y, S2[2*q+3], yd);
            }
        } else {
            #pragma unroll
            for (int q = 0; q < 16; q += 2) {
                ulonglong2 rq = r2p[q], kq = k2p[q], wq = w2p[q];
                ulonglong2 rq1 = r2p[q+1], kq1 = k2p[q+1], wq1 = w2p[q+1];
                ya = fma2v(rq.x, S2[2*q+0], ya);
                S2[2*q+0] = mul2(wq.x, fma2v(kq.x, v2, S2[2*q+0]));
                yb = fma2v(rq.y, S2[2*q+1], yb);
                S2[2*q+1] = mul2(wq.y, fma2v(kq.y, v2, S2[2*q+1]));
                yc = fma2v(rq1.x, S2[2*q+2], yc);
                S2[2*q+2] = mul2(wq1.x, fma2v(kq1.x, v2, S2[2*q+2]));
                yd = fma2v(rq1.y, S2[2*q+3], yd);
                S2[2*q+3] = mul2(wq1.y, fma2v(kq1.y, v2, S2[2*q+3]));
            }
        }

        float y0, y1, y2, y3, y4, y5, y6, y7;
        unpk2(ya, y0, y1); unpk2(yb, y2, y3);
        unpk2(yc, y4, y5); unpk2(yd, y6, y7);
        float y = ((y0 + y1) + (y2 + y3)) + ((y4 + y5) + (y6 + y7));

        int tr = dir ? (Tq - 1 - t) : t;
        size_t off = base + (size_t)tr * Dq + j;
        if (dir == 0) g_yf[off] = y;
        else          g_yb[off] = y;
    }
}

// ---------------- groupnorm + output gate + silu-gate (→ z hi/lo) ---------------
__global__ void __launch_bounds__(128) gn_kernel(const float* __restrict__ ln_w,
                                                 const float* __restrict__ ln_b)
{
    int gidx = blockIdx.x * 4 + (threadIdx.x >> 5);
    int lane = threadIdx.x & 31;
    int bt = gidx / Hq, h = gidx % Hq;
    size_t rowbase = (size_t)bt * Dq + (size_t)h * Kq;
    size_t i0 = rowbase + lane, i1 = rowbase + lane + 32;

    float a = (g_yf[i0] + g_yb[i0]) * g_gate[i0];
    float c = (g_yf[i1] + g_yb[i1]) * g_gate[i1];
    float s = a + c, sq = a * a + c * c;
    #pragma unroll
    for (int o = 16; o; o >>= 1) {
        s  += __shfl_xor_sync(0xffffffffu, s,  o);
        sq += __shfl_xor_sync(0xffffffffu, sq, o);
    }
    float mean = s * (1.f / 64.f);
    float var  = sq * (1.f / 64.f) - mean * mean;
    float rstd = rsqrtf(var + 6.4e-4f);
    int d0 = h * Kq + lane, d1 = d0 + 32;
    float z0 = ((a - mean) * rstd * ln_w[d0] + ln_b[d0]) * g_g[i0];
    float z1 = ((c - mean) * rstd * ln_w[d1] + ln_b[d1]) * g_g[i1];
    __nv_bfloat16 h0 = __float2bfloat16(z0);
    __nv_bfloat16 h1 = __float2bfloat16(z1);
    g_zh[i0] = h0; g_zl[i0] = __float2bfloat16(z0 - __bfloat162float(h0));
    g_zh[i1] = h1; g_zl[i1] = __float2bfloat16(z1 - __bfloat162float(h1));
}

// ---------------- launch --------------------------------------------------------
extern "C" void kernel_launch(void* const* d_in, const int* in_sizes, int n_in,
                              void* d_out, int out_size)
{
    const float* x          = (const float*)d_in[0];
    const float* conv_w     = (const float*)d_in[1];
    const float* maa_x      = (const float*)d_in[2];
    const float* maa_w      = (const float*)d_in[3];
    const float* maa_k      = (const float*)d_in[4];
    const float* maa_v      = (const float*)d_in[5];
    const float* maa_r      = (const float*)d_in[6];
    const float* maa_g      = (const float*)d_in[7];
    const float* maa_w1     = (const float*)d_in[8];
    const float* maa_w2     = (const float*)d_in[9];
    const float* time_decay = (const float*)d_in[10];
    const float* decay_w1   = (const float*)d_in[11];
    const float* decay_w2   = (const float*)d_in[12];
    const float* Wr         = (const float*)d_in[13];
    const float* Wk         = (const float*)d_in[14];
    const float* Wv         = (const float*)d_in[15];
    const float* Wg         = (const float*)d_in[16];
    const float* Wo         = (const float*)d_in[17];
    const float* ln_w       = (const float*)d_in[18];
    const float* ln_b       = (const float*)d_in[19];
    const float* gate_w     = (const float*)d_in[20];
    const float* gate_b     = (const float*)d_in[21];
    float* out = (float*)d_out;

    float *p_t5, *p_xw, *p_r, *p_k, *p_v, *p_g, *p_h, *p_ww, *p_gate;
    __nv_bfloat16 *p_xxh, *p_xxl, *p_dxh, *p_dxl, *p_xkh, *p_xkl, *p_xvh, *p_xvl;
    __nv_bfloat16 *p_xrh, *p_xrl, *p_xgh, *p_xgl, *p_zh, *p_zl, *p_wh, *p_wl;
    __nv_bfloat16 *p_w1h, *p_w1l;
    cudaGetSymbolAddress((void**)&p_t5,   g_t5);
    cudaGetSymbolAddress((void**)&p_xw,   g_xw);
    cudaGetSymbolAddress((void**)&p_r,    g_r);
    cudaGetSymbolAddress((void**)&p_k,    g_k);
    cudaGetSymbolAddress((void**)&p_v,    g_v);
    cudaGetSymbolAddress((void**)&p_g,    g_g);
    cudaGetSymbolAddress((void**)&p_h,    g_hbuf);
    cudaGetSymbolAddress((void**)&p_ww,   g_ww);
    cudaGetSymbolAddress((void**)&p_gate, g_gate);
    cudaGetSymbolAddress((void**)&p_xxh,  g_xxh);
    cudaGetSymbolAddress((void**)&p_xxl,  g_xxl);
    cudaGetSymbolAddress((void**)&p_dxh,  g_dxh);
    cudaGetSymbolAddress((void**)&p_dxl,  g_dxl);
    cudaGetSymbolAddress((void**)&p_xkh,  g_xkh);
    cudaGetSymbolAddress((void**)&p_xkl,  g_xkl);
    cudaGetSymbolAddress((void**)&p_xvh,  g_xvh);
    cudaGetSymbolAddress((void**)&p_xvl,  g_xvl);
    cudaGetSymbolAddress((void**)&p_xrh,  g_xrh);
    cudaGetSymbolAddress((void**)&p_xrl,  g_xrl);
    cudaGetSymbolAddress((void**)&p_xgh,  g_xgh);
    cudaGetSymbolAddress((void**)&p_xgl,  g_xgl);
    cudaGetSymbolAddress((void**)&p_zh,   g_zh);
    cudaGetSymbolAddress((void**)&p_zl,   g_zl);
    cudaGetSymbolAddress((void**)&p_wh,   g_wh);
    cudaGetSymbolAddress((void**)&p_wl,   g_wl);
    cudaGetSymbolAddress((void**)&p_w1h,  g_w1h);
    cudaGetSymbolAddress((void**)&p_w1l,  g_w1l);

    cudaFuncSetAttribute((const void*)hmma_gemm<TEPI_NONE,3>, cudaFuncAttributeMaxDynamicSharedMemorySize, HM_SMEM);
    cudaFuncSetAttribute((const void*)hmma_gemm<TEPI_SILU,3>, cudaFuncAttributeMaxDynamicSharedMemorySize, HM_SMEM);
    cudaFuncSetAttribute((const void*)hmma_gemm<TEPI_GATE,3>, cudaFuncAttributeMaxDynamicSharedMemorySize, HM_SMEM);
    cudaFuncSetAttribute((const void*)hmma_gemm<TEPI_TANH,4>, cudaFuncAttributeMaxDynamicSharedMemorySize, HM_SMEM);

    // 0) conv / dx fp32+hi/lo / xxx hi/lo
    {
        int threads = 256;
        int blocks  = (int)((BTDq + threads - 1) / threads);
        conv_kernel<<<blocks, threads>>>(x, conv_w, maa_x);
    }

    // 1) weight transpose + split
    {
        dim3 g(32, 32, 6);
        wsplit_kernel<<<g, 256>>>(Wr, Wk, Wv, Wg, gate_w, Wo);
    }
    // 2) maa_w1 transpose + split
    {
        dim3 g(5, 32);
        wsplit_w1_kernel<<<g, 256>>>(maa_w1);
    }

    dim3 blk(256);
    dim3 grid_64(1, Mq / BMt);
    dim3 grid_dec(Dq / BNt, Mq / BMt);
    dim3 hm_grid(8, Mq / 128);
    dim3 hm_t5(2, Mq / 128);

    // 3) t5 = tanh(xxx @ maa_w1)  [HMMA 4-pass, N=160]
    hmma_gemm<TEPI_TANH,4><<<hm_t5, 256, HM_SMEM>>>(p_xxh, p_xxl, p_w1h, p_w1l,
                                                    p_t5, nullptr, 160, 160);

    // 4) fused token-mix: xw fp32 (exact dx); xk/xv/xr/xg as bf16 hi/lo
    {
        dim3 g(Dq / 128, Mq / 64);
        mix5_kernel<<<g, 256>>>(maa_w2, x, maa_w, maa_k, maa_v, maa_r, maa_g);
    }

    const size_t WS = 1024 * 1024;
    // 5) big projections (3-pass; fp32 dx anchors accuracy per R4/R13 evidence)
    hmma_gemm<TEPI_NONE,3><<<hm_grid, 256, HM_SMEM>>>(p_xrh, p_xrl, p_wh + 0*WS, p_wl + 0*WS, p_r, nullptr, 1024, 1024);
    hmma_gemm<TEPI_NONE,3><<<hm_grid, 256, HM_SMEM>>>(p_xkh, p_xkl, p_wh + 1*WS, p_wl + 1*WS, p_k, nullptr, 1024, 1024);
    hmma_gemm<TEPI_NONE,3><<<hm_grid, 256, HM_SMEM>>>(p_xvh, p_xvl, p_wh + 2*WS, p_wl + 2*WS, p_v, nullptr, 1024, 1024);
    hmma_gemm<TEPI_SILU,3><<<hm_grid, 256, HM_SMEM>>>(p_xgh, p_xgl, p_wh + 3*WS, p_wl + 3*WS, p_g, nullptr, 1024, 1024);
    hmma_gemm<TEPI_GATE,3><<<hm_grid, 256, HM_SMEM>>>(p_dxh, p_dxl, p_wh + 4*WS, p_wl + 4*WS, p_gate, gate_b, 1024, 1024);

    // 6) decay MLP (scalar fp32 for precision)
    sgemm<EPI_TANH><<<grid_64, blk>>>(p_xw, Dq, decay_w1, 64, p_h, 64,
                                      64, Dq, nullptr);
    sgemm<EPI_DECAY><<<grid_dec, blk>>>(p_h, 64, decay_w2, Dq, p_ww, Dq,
                                        Dq, 64, time_decay);

    // 7) bidirectional recurrence
    {
        dim3 g(Bq * Hq, 2);
        wkv_kernel<<<g, 64>>>();
    }

    // 8) gate + groupnorm + silu-gate → z hi/lo
    gn_kernel<<<(Mq * Hq) / 4, 128>>>(ln_w, ln_b);

    // 9) out = z @ Wo (HMMA 3-pass)
    hmma_gemm<TEPI_NONE,3><<<hm_grid, 256, HM_SMEM>>>(p_zh, p_zl, p_wh + 5*WS, p_wl + 5*WS, out, nullptr, 1024, 1024);
}

// round 15
// speedup vs baseline: 1.5881x; 1.0010x over previous
#include <cuda_runtime.h>
#include <cuda_bf16.h>
#include <math.h>
#include <stdint.h>

// Problem constants
#define Bq 8
#define Tq 2048
#define Dq 1024
#define Hq 16
#define Kq 64
#define Mq (Bq*Tq)                 // 16384 rows
#define BTDq ((size_t)Mq*(size_t)Dq)

// ---------------- scratch (device globals; no allocations allowed) -------------
__device__ float g_dx  [Mq*Dq];
__device__ float g_t5  [Mq*160];
__device__ float g_xw  [Mq*Dq];
__device__ float g_r   [Mq*Dq];
__device__ float g_k   [Mq*Dq];
__device__ float g_v   [Mq*Dq];
__device__ float g_g   [Mq*Dq];
__device__ float g_hbuf[Mq*64];
__device__ float g_ww  [Mq*Dq];
__device__ float g_gate[Mq*Dq];
__device__ float g_yf  [Mq*Dq];
__device__ float g_yb  [Mq*Dq];

// bf16 hi/lo split activations
__device__ __nv_bfloat16 g_xxh[Mq*Dq], g_xxl[Mq*Dq];
__device__ __nv_bfloat16 g_dxh[Mq*Dq], g_dxl[Mq*Dq];
__device__ __nv_bfloat16 g_xkh[Mq*Dq], g_xkl[Mq*Dq];
__device__ __nv_bfloat16 g_xvh[Mq*Dq], g_xvl[Mq*Dq];
__device__ __nv_bfloat16 g_xrh[Mq*Dq], g_xrl[Mq*Dq];
__device__ __nv_bfloat16 g_xgh[Mq*Dq], g_xgl[Mq*Dq];
__device__ __nv_bfloat16 g_zh [Mq*Dq], g_zl [Mq*Dq];
// transposed weights [N,K] hi/lo, 6 slots: Wr,Wk,Wv,Wg,gate_w,Wo
__device__ __nv_bfloat16 g_wh[6*1024*1024], g_wl[6*1024*1024];
// maa_w1 transposed [160(+pad to 256),1024] hi/lo
__device__ __nv_bfloat16 g_w1h[256*1024], g_w1l[256*1024];

// ---------------- helpers -------------------------------------------------------
__device__ __forceinline__ uint32_t smem_u32(const void* p) {
    uint32_t a;
    asm("{ .reg .u64 t; cvta.to.shared.u64 t, %1; cvt.u32.u64 %0, t; }" : "=r"(a) : "l"(p));
    return a;
}
__device__ __forceinline__ void cp16(uint32_t dst, const void* src) {
    asm volatile("cp.async.cg.shared.global [%0], [%1], 16;" :: "r"(dst), "l"(src));
}
__device__ __forceinline__ void cp4(uint32_t dst, const void* src) {
    asm volatile("cp.async.ca.shared.global [%0], [%1], 4;" :: "r"(dst), "l"(src));
}
#define CP_COMMIT() asm volatile("cp.async.commit_group;" ::: "memory")
#define CP_WAIT(n)  asm volatile("cp.async.wait_group %0;" :: "n"(n) : "memory")

#define LDSM4(R0, R1, R2, R3, ADDR) \
    asm volatile("ldmatrix.sync.aligned.m8n8.x4.shared.b16 {%0,%1,%2,%3}, [%4];" \
        : "=r"(R0), "=r"(R1), "=r"(R2), "=r"(R3) : "r"(ADDR))

#define MMA_BF16(D, A, B0, B1) \
    asm volatile("mma.sync.aligned.m16n8k16.row.col.f32.bf16.bf16.f32 " \
        "{%0,%1,%2,%3}, {%4,%5,%6,%7}, {%8,%9}, {%0,%1,%2,%3};" \
        : "+f"((D)[0]), "+f"((D)[1]), "+f"((D)[2]), "+f"((D)[3]) \
        : "r"((A)[0]), "r"((A)[1]), "r"((A)[2]), "r"((A)[3]), "r"(B0), "r"(B1))

// packed f32x2 helpers
__device__ __forceinline__ unsigned long long pk2(float lo, float hi) {
    unsigned long long r;
    asm("mov.b64 %0, {%1, %2};" : "=l"(r) : "f"(lo), "f"(hi));
    return r;
}
__device__ __forceinline__ void fma2(unsigned long long& d,
                                     unsigned long long a,
                                     unsigned long long b) {
    asm("fma.rn.f32x2 %0, %1, %2, %0;" : "+l"(d) : "l"(a), "l"(b));
}
__device__ __forceinline__ unsigned long long fma2v(unsigned long long a,
                                                    unsigned long long b,
                                                    unsigned long long c) {
    unsigned long long d;
    asm("fma.rn.f32x2 %0, %1, %2, %3;" : "=l"(d) : "l"(a), "l"(b), "l"(c));
    return d;
}
__device__ __forceinline__ unsigned long long mul2(unsigned long long a,
                                                   unsigned long long b) {
    unsigned long long d;
    asm("mul.rn.f32x2 %0, %1, %2;" : "=l"(d) : "l"(a), "l"(b));
    return d;
}
__device__ __forceinline__ void unpk2(unsigned long long v, float& lo, float& hi) {
    asm("mov.b64 {%0, %1}, %2;" : "=f"(lo), "=f"(hi) : "l"(v));
}

// hi/lo split store of 4 consecutive floats
__device__ __forceinline__ void store_split4(__nv_bfloat16* H, __nv_bfloat16* L,
                                             size_t idx, float4 o) {
    __nv_bfloat162 h01 = __floats2bfloat162_rn(o.x, o.y);
    __nv_bfloat162 h23 = __floats2bfloat162_rn(o.z, o.w);
    float2 f01 = __bfloat1622float2(h01);
    float2 f23 = __bfloat1622float2(h23);
    __nv_bfloat162 l01 = __floats2bfloat162_rn(o.x - f01.x, o.y - f01.y);
    __nv_bfloat162 l23 = __floats2bfloat162_rn(o.z - f23.x, o.w - f23.y);
    uint2 hv = make_uint2(*(unsigned*)&h01, *(unsigned*)&h23);
    uint2 lv = make_uint2(*(unsigned*)&l01, *(unsigned*)&l23);
    *(uint2*)&H[idx] = hv;
    *(uint2*)&L[idx] = lv;
}

// ---------------- kernel: depthwise conv (k=3), dx fp32+hi/lo, xxx hi/lo -------
__global__ void conv_kernel(const float* __restrict__ x,
                            const float* __restrict__ cw,
                            const float* __restrict__ maa_x)
{
    size_t idx = (size_t)blockIdx.x * blockDim.x + threadIdx.x;
    if (idx >= BTDq) return;
    int d = (int)(idx & (Dq - 1));
    int t = (int)((idx / Dq) & (Tq - 1));
    float x0 = x[idx];
    float xm = (t > 0)      ? x[idx - Dq] : 0.f;
    float xp = (t < Tq - 1) ? x[idx + Dq] : 0.f;
    float dxv = cw[d*3+0]*xm + cw[d*3+1]*x0 + cw[d*3+2]*xp - x0;
    float xxx = x0 + dxv * maa_x[d];
    g_dx[idx] = dxv;
    __nv_bfloat16 h = __float2bfloat16(dxv);
    g_dxh[idx] = h;
    g_dxl[idx] = __float2bfloat16(dxv - __bfloat162float(h));
    __nv_bfloat16 xh = __float2bfloat16(xxx);
    g_xxh[idx] = xh;
    g_xxl[idx] = __float2bfloat16(xxx - __bfloat162float(xh));
}

// ---------------- kernel: weight transpose + bf16 split (6 slots) --------------
__global__ void __launch_bounds__(256) wsplit_kernel(
    const float* __restrict__ W0, const float* __restrict__ W1,
    const float* __restrict__ W2, const float* __restrict__ W3,
    const float* __restrict__ W4, const float* __restrict__ W5)
{
    __shared__ float tile[32][33];
    const float* Ws[6] = { W0, W1, W2, W3, W4, W5 };
    const float* W = Ws[blockIdx.z];
    __nv_bfloat16* H = g_wh + (size_t)blockIdx.z * 1024 * 1024;
    __nv_bfloat16* L = g_wl + (size_t)blockIdx.z * 1024 * 1024;
    int n0 = blockIdx.x * 32, k0 = blockIdx.y * 32;
    int tx = threadIdx.x & 31, ty = threadIdx.x >> 5;
    #pragma unroll
    for (int i = 0; i < 4; i++)
        tile[ty + i*8][tx] = W[(size_t)(k0 + ty + i*8) * 1024 + n0 + tx];
    __syncthreads();
    #pragma unroll
    for (int i = 0; i < 4; i++) {
        float v = tile[tx][ty + i*8];
        __nv_bfloat16 h = __float2bfloat16(v);
        size_t o = (size_t)(n0 + ty + i*8) * 1024 + k0 + tx;
        H[o] = h;
        L[o] = __float2bfloat16(v - __bfloat162float(h));
    }
}

// ---------------- kernel: maa_w1 [1024,160] -> [160,1024] hi/lo ----------------
__global__ void __launch_bounds__(256) wsplit_w1_kernel(const float* __restrict__ W1)
{
    __shared__ float tile[32][33];
    int n0 = blockIdx.x * 32, k0 = blockIdx.y * 32;   // n<160, k<1024
    int tx = threadIdx.x & 31, ty = threadIdx.x >> 5;
    #pragma unroll
    for (int i = 0; i < 4; i++)
        tile[ty + i*8][tx] = W1[(size_t)(k0 + ty + i*8) * 160 + n0 + tx];
    __syncthreads();
    #pragma unroll
    for (int i = 0; i < 4; i++) {
        float v = tile[tx][ty + i*8];
        __nv_bfloat16 h = __float2bfloat16(v);
        size_t o = (size_t)(n0 + ty + i*8) * 1024 + k0 + tx;
        g_w1h[o] = h;
        g_w1l[o] = __float2bfloat16(v - __bfloat162float(h));
    }
}

// ---------------- HMMA bf16 split GEMM (mma.sync), 3-stage pipeline ------------
// PASSES=3: AhBh + AhBl + AlBh.  PASSES=4: + AlBl
#define HM_SMEM 98304
enum { TEPI_NONE = 0, TEPI_SILU, TEPI_GATE, TEPI_TANH };

template<int EPI>
__device__ __forceinline__ float tepi(float a, int col, const float* __restrict__ vec) {
    if (EPI == TEPI_SILU) return a / (1.f + __expf(-a));
    if (EPI == TEPI_GATE) return 1.f / (1.f + __expf(-(a + vec[col])));
    if (EPI == TEPI_TANH) return tanhf(a);
    return a;
}

template<int EPI, int PASSES>
__global__ void __launch_bounds__(256, 2) hmma_gemm(
    const __nv_bfloat16* __restrict__ Ah, const __nv_bfloat16* __restrict__ Al,
    const __nv_bfloat16* __restrict__ Bh, const __nv_bfloat16* __restrict__ Bl,
    float* __restrict__ C, const float* __restrict__ vec,
    int N, int ldc)
{
    extern __shared__ __align__(128) char sm[];
    const uint32_t sb = smem_u32(sm);
    const int tid = threadIdx.x, lane = tid & 31, wid = tid >> 5;
    const int m0 = blockIdx.y * 128, n0 = blockIdx.x * 128;
    const int wm = (wid & 1) * 64;
    const int wn = (wid >> 1) * 32;

    const int ldrow = (tid >> 2);
    const int ldk16 = tid & 3;

    float acc[4][4][4];
    #pragma unroll
    for (int a = 0; a < 4; a++)
        #pragma unroll
        for (int b = 0; b < 4; b++)
            #pragma unroll
            for (int c = 0; c < 4; c++) acc[a][b][c] = 0.f;

    auto load_chunk = [&](int c) {
        const uint32_t base = sb + (uint32_t)(c % 3) * 32768;
        const int kc = c * 32;
        #pragma unroll
        for (int h = 0; h < 2; h++) {
            int row = ldrow + h * 64;
            uint32_t sw = (uint32_t)row * 64 + (uint32_t)((ldk16 ^ ((row >> 1) & 3)) << 4);
            size_t ga = (size_t)(m0 + row) * 1024 + kc + ldk16 * 8;
            size_t gb = (size_t)(n0 + row) * 1024 + kc + ldk16 * 8;
            cp16(base +         sw, Ah + ga);
            cp16(base +  8192 + sw, Al + ga);
            cp16(base + 16384 + sw, Bh + gb);
            cp16(base + 24576 + sw, Bl + gb);
        }
        CP_COMMIT();
    };

    load_chunk(0);
    load_chunk(1);

    const int rowl = lane & 15;
    const int s3 = (rowl >> 1) & 3;
    const int chnk = lane >> 4;

    for (int c = 0; c < 32; c++) {
        CP_WAIT(1);
        __syncthreads();
        if (c + 2 < 32) load_chunk(c + 2);

        const uint32_t st = sb + (uint32_t)(c % 3) * 32768;
        const uint32_t aBase = st + (uint32_t)(wm + rowl) * 64;
        const uint32_t bBase = st + 16384 + (uint32_t)(wn + rowl) * 64;

        #pragma unroll
        for (int ks = 0; ks < 2; ks++) {
            const uint32_t sw = (uint32_t)(((2 * ks + chnk) ^ s3) << 4);
            uint32_t ah[4][4], al[4][4], bh[2][4], bl[2][4];
            #pragma unroll
            for (int mi = 0; mi < 4; mi++) {
                LDSM4(ah[mi][0], ah[mi][1], ah[mi][2], ah[mi][3], aBase + mi * 1024 + sw);
                LDSM4(al[mi][0], al[mi][1], al[mi][2], al[mi][3], aBase + 8192 + mi * 1024 + sw);
            }
            #pragma unroll
            for (int nf = 0; nf < 2; nf++) {
                LDSM4(bh[nf][0], bh[nf][1], bh[nf][2], bh[nf][3], bBase + nf * 1024 + sw);
                LDSM4(bl[nf][0], bl[nf][1], bl[nf][2], bl[nf][3], bBase + 8192 + nf * 1024 + sw);
            }
            #pragma unroll
            for (int mi = 0; mi < 4; mi++) {
                #pragma unroll
                for (int nj = 0; nj < 4; nj++) {
                    uint32_t b0h = bh[nj >> 1][nj & 1], b1h = bh[nj >> 1][(nj & 1) + 2];
                    uint32_t b0l = bl[nj >> 1][nj & 1], b1l = bl[nj >> 1][(nj & 1) + 2];
                    MMA_BF16(acc[mi][nj], ah[mi], b0h, b1h);
                    MMA_BF16(acc[mi][nj], ah[mi], b0l, b1l);
                    MMA_BF16(acc[mi][nj], al[mi], b0h, b1h);
                    if (PASSES == 4) MMA_BF16(acc[mi][nj], al[mi], b0l, b1l);
                }
            }
        }
    }

    const int er = lane >> 2, ec = (lane & 3) * 2;
    #pragma unroll
    for (int mi = 0; mi < 4; mi++) {
        #pragma unroll
        for (int nj = 0; nj < 4; nj++) {
            int row = m0 + wm + mi * 16 + er;
            int col = n0 + wn + nj * 8 + ec;
            if (col < N) {
                float2 o0, o1;
                o0.x = tepi<EPI>(acc[mi][nj][0], col,     vec);
                o0.y = tepi<EPI>(acc[mi][nj][1], col + 1, vec);
                o1.x = tepi<EPI>(acc[mi][nj][2], col,     vec);
                o1.y = tepi<EPI>(acc[mi][nj][3], col + 1, vec);
                *(float2*)&C[(size_t)row * ldc + col]       = o0;
                *(float2*)&C[(size_t)(row + 8) * ldc + col] = o1;
            }
        }
    }
}

// ---------------- scalar SGEMM (FFMA2) for decay GEMMs (fp32 precision) --------
#define BMt 128
#define BNt 128
#define BKt 16
enum { EPI_NONE = 0, EPI_TANH, EPI_DECAY };

template<int EPI>
__device__ __forceinline__ float epi_apply(float acc, int col,
                                           const float* __restrict__ vec)
{
    if (EPI == EPI_TANH)  return tanhf(acc);
    if (EPI == EPI_DECAY) return __expf(-__expf(vec[col] + acc));
    return acc;
}

template<int EPI>
__global__ void __launch_bounds__(256, 2) sgemm(
    const float* __restrict__ A, int lda,
    const float* __restrict__ Bm, int ldb,
    float* __restrict__ C, int ldc,
    int N, int Kd,
    const float* __restrict__ vec)
{
    __shared__ float As[BKt][BMt];
    __shared__ float Bs[BKt][BNt];

    int tid = threadIdx.x;
    int m0  = blockIdx.y * BMt;
    int n0  = blockIdx.x * BNt;

    int a_row = tid >> 2;
    int a_col = (tid & 3) << 2;
    int b_row = tid >> 5;
    int b_col = (tid & 31) << 2;
    int ty = tid >> 4, tx = tid & 15;

    const float* Aptr = A + (size_t)m0 * lda;
    bool bvalid = (n0 + b_col) < N;
    const float4 z4 = make_float4(0.f, 0.f, 0.f, 0.f);

    float4 a_reg[2], b_reg[2];
    a_reg[0] = *(const float4*)(Aptr + (size_t)a_row       * lda + a_col);
    a_reg[1] = *(const float4*)(Aptr + (size_t)(a_row + 64) * lda + a_col);
    b_reg[0] = bvalid ? *(const float4*)(Bm + (size_t)b_row       * ldb + n0 + b_col) : z4;
    b_reg[1] = bvalid ? *(const float4*)(Bm + (size_t)(b_row + 8) * ldb + n0 + b_col) : z4;

    #pragma unroll
    for (int jj = 0; jj < 4; jj++) {
        As[a_col + jj][a_row]      = ((const float*)&a_reg[0])[jj];
        As[a_col + jj][a_row + 64] = ((const float*)&a_reg[1])[jj];
    }
    *(float4*)&Bs[b_row][b_col]     = b_reg[0];
    *(float4*)&Bs[b_row + 8][b_col] = b_reg[1];
    __syncthreads();

    unsigned long long acc2[8][4];
    #pragma unroll
    for (int i = 0; i < 8; i++)
        #pragma unroll
        for (int j = 0; j < 4; j++)
            acc2[i][j] = 0ull;

    for (int k0 = 0;;) {
        int knext = k0 + BKt;
        if (knext < Kd) {
            a_reg[0] = *(const float4*)(Aptr + (size_t)a_row       * lda + knext + a_col);
            a_reg[1] = *(const float4*)(Aptr + (size_t)(a_row + 64) * lda + knext + a_col);
            b_reg[0] = bvalid ? *(const float4*)(Bm + (size_t)(knext + b_row)     * ldb + n0 + b_col) : z4;
            b_reg[1] = bvalid ? *(const float4*)(Bm + (size_t)(knext + b_row + 8) * ldb + n0 + b_col) : z4;
        }
        #pragma unroll
        for (int kk = 0; kk < BKt; kk++) {
            float a_f[8], b_f[8];
            *(float4*)&a_f[0] = *(const float4*)&As[kk][ty * 8];
            *(float4*)&a_f[4] = *(const float4*)&As[kk][ty * 8 + 4];
            *(float4*)&b_f[0] = *(const float4*)&Bs[kk][tx * 8];
            *(float4*)&b_f[4] = *(const float4*)&Bs[kk][tx * 8 + 4];
            unsigned long long b2[4];
            #pragma unroll
            for (int j = 0; j < 4; j++) b2[j] = pk2(b_f[2*j], b_f[2*j+1]);
            #pragma unroll
            for (int i = 0; i < 8; i++) {
                unsigned long long a2 = pk2(a_f[i], a_f[i]);
                #pragma unroll
                for (int j = 0; j < 4; j++) fma2(acc2[i][j], a2, b2[j]);
            }
        }
        if (knext >= Kd) break;
        __syncthreads();
        #pragma unroll
        for (int jj = 0; jj < 4; jj++) {
            As[a_col + jj][a_row]      = ((const float*)&a_reg[0])[jj];
            As[a_col + jj][a_row + 64] = ((const float*)&a_reg[1])[jj];
        }
        *(float4*)&Bs[b_row][b_col]     = b_reg[0];
        *(float4*)&Bs[b_row + 8][b_col] = b_reg[1];
        __syncthreads();
        k0 = knext;
    }

    float acc[8][8];
    #pragma unroll
    for (int i = 0; i < 8; i++)
        #pragma unroll
        for (int j = 0; j < 4; j++)
            unpk2(acc2[i][j], acc[i][2*j], acc[i][2*j+1]);

    #pragma unroll
    for (int i = 0; i < 8; i++) {
        int row = m0 + ty * 8 + i;
        #pragma unroll
        for (int j = 0; j < 8; j += 4) {
            int col = n0 + tx * 8 + j;
            if (col < N) {
                float4 o;
                o.x = epi_apply<EPI>(acc[i][j + 0], col + 0, vec);
                o.y = epi_apply<EPI>(acc[i][j + 1], col + 1, vec);
                o.z = epi_apply<EPI>(acc[i][j + 2], col + 2, vec);
                o.w = epi_apply<EPI>(acc[i][j + 3], col + 3, vec);
                *(float4*)&C[(size_t)row * ldc + col] = o;
            }
        }
    }
}

// ---------------- fused 5-way token-mix kernel (fp32 dx, R10 form) --------------
__global__ void __launch_bounds__(256) mix5_kernel(
    const float* __restrict__ maa_w2,
    const float* __restrict__ x,
    const float* __restrict__ mw, const float* __restrict__ mk,
    const float* __restrict__ mv, const float* __restrict__ mr,
    const float* __restrict__ mg)
{
    __shared__ float t5s[64][160];
    __shared__ float Bs[32][128];

    int m0 = blockIdx.y * 64;
    int n0 = blockIdx.x * 128;
    int tid = threadIdx.x;

    for (int i = tid; i < 64 * 40; i += 256) {
        int r = i / 40, c4 = (i % 40) * 4;
        *(float4*)&t5s[r][c4] = *(const float4*)&g_t5[(size_t)(m0 + r) * 160 + c4];
    }

    int colg = (tid & 31) * 4;
    int row0 = (tid >> 5) * 8;

    const float* maas[5] = { mw, mk, mv, mr, mg };
    __nv_bfloat16* outH[5] = { nullptr, g_xkh, g_xvh, g_xrh, g_xgh };
    __nv_bfloat16* outL[5] = { nullptr, g_xkl, g_xvl, g_xrl, g_xgl };

    #pragma unroll
    for (int f = 0; f < 5; f++) {
        __syncthreads();
        for (int i = tid; i < 32 * 32; i += 256) {
            int k = i / 32, c4 = (i % 32) * 4;
            *(float4*)&Bs[k][c4] =
                *(const float4*)&maa_w2[((size_t)f * 32 + k) * Dq + n0 + c4];
        }
        __syncthreads();

        float acc0[8], acc1[8], acc2_[8], acc3[8];
        #pragma unroll
        for (int r = 0; r < 8; r++) { acc0[r]=0.f; acc1[r]=0.f; acc2_[r]=0.f; acc3[r]=0.f; }

        #pragma unroll 4
        for (int k = 0; k < 32; k++) {
            float4 b4 = *(const float4*)&Bs[k][colg];
            #pragma unroll
            for (int r = 0; r < 8; r++) {
                float a = t5s[row0 + r][f * 32 + k];
                acc0[r] = fmaf(a, b4.x, acc0[r]);
                acc1[r] = fmaf(a, b4.y, acc1[r]);
                acc2_[r] = fmaf(a, b4.z, acc2_[r]);
                acc3[r] = fmaf(a, b4.w, acc3[r]);
            }
        }

        float4 mva = *(const float4*)&maas[f][n0 + colg];
        #pragma unroll
        for (int r = 0; r < 8; r++) {
            size_t idx = (size_t)(m0 + row0 + r) * Dq + n0 + colg;
            float4 xv4 = *(const float4*)&x[idx];
            float4 dx4 = *(const float4*)&g_dx[idx];
            float4 o;
            o.x = xv4.x + dx4.x * (mva.x + acc0[r]);
            o.y = xv4.y + dx4.y * (mva.y + acc1[r]);
            o.z = xv4.z + dx4.z * (mva.z + acc2_[r]);
            o.w = xv4.w + dx4.w * (mva.w + acc3[r]);
            if (f == 0) *(float4*)&g_xw[idx] = o;
            else        store_split4(outH[f], outL[f], idx, o);
        }
    }
}

// ---------------- bidirectional WKV recurrence (64 thr, cp.async, f32x2) -------
__global__ void __launch_bounds__(64) wkv_kernel()
{
    int bh  = blockIdx.x;
    int dir = blockIdx.y;
    int b = bh / Hq, h = bh % Hq;
    size_t base = (size_t)b * Tq * Dq + (size_t)h * Kq;
    int j = threadIdx.x;

    __shared__ __align__(16) float s_r[4][Kq], s_k[4][Kq], s_w[4][Kq], s_v[4][Kq];
    const uint32_t a_r = smem_u32(s_r), a_k = smem_u32(s_k);
    const uint32_t a_w = smem_u32(s_w), a_v = smem_u32(s_v);

    unsigned long long S2[32];
    #pragma unroll
    for (int i = 0; i < 32; i++) S2[i] = 0ull;

    auto issue = [&](int t) {
        int st = t & 3;
        int tr = dir ? (Tq - 1 - t) : t;
        size_t off = base + (size_t)tr * Dq + j;
        uint32_t so = (uint32_t)(st * Kq + j) * 4;
        cp4(a_r + so, &g_r[off]);
        cp4(a_k + so, &g_k[off]);
        cp4(a_w + so, &g_ww[off]);
        cp4(a_v + so, &g_v[off]);
        CP_COMMIT();
    };

    issue(0); issue(1); issue(2);

    for (int t = 0; t < Tq; t++) {
        int st = t & 3;
        CP_WAIT(2);
        __syncthreads();
        if (t + 3 < Tq) issue(t + 3);

        float vj = s_v[st][j];
        unsigned long long v2 = pk2(vj, vj);
        const ulonglong2* r2p = (const ulonglong2*)s_r[st];
        const ulonglong2* k2p = (const ulonglong2*)s_k[st];
        const ulonglong2* w2p = (const ulonglong2*)s_w[st];

        unsigned long long ya = 0ull, yb = 0ull, yc = 0ull, yd = 0ull;

        if (dir == 0) {
            #pragma unroll
            for (int q = 0; q < 16; q += 2) {
                ulonglong2 rq = r2p[q], kq = k2p[q], wq = w2p[q];
                ulonglong2 rq1 = r2p[q+1], kq1 = k2p[q+1], wq1 = w2p[q+1];
                S2[2*q+0] = fma2v(wq.x, S2[2*q+0], mul2(kq.x, v2));
                ya = fma2v(rq.x, S2[2*q+0], ya);
                S2[2*q+1] = fma2v(wq.y, S2[2*q+1], mul2(kq.y, v2));
                yb = fma2v(rq.y, S2[2*q+1], yb);
                S2[2*q+2] = fma2v(wq1.x, S2[2*q+2], mul2(kq1.x, v2));
                yc = fma2v(rq1.x, S2[2*q+2], yc);
                S2[2*q+3] = fma2v(wq1.y, S2[2*q+3], mul2(kq1.y, v2));
                yd = fma2v(rq1.y, S2[2*q+3], yd);
            }
        } else {
            #pragma unroll
            for (int q = 0; q < 16; q += 2) {
                ulonglong2 rq = r2p[q], kq = k2p[q], wq = w2p[q];
                ulonglong2 rq1 = r2p[q+1], kq1 = k2p[q+1], wq1 = w2p[q+1];
                ya = fma2v(rq.x, S2[2*q+0], ya);
                S2[2*q+0] = mul2(wq.x, fma2v(kq.x, v2, S2[2*q+0]));
                yb = fma2v(rq.y, S2[2*q+1], yb);
                S2[2*q+1] = mul2(wq.y, fma2v(kq.y, v2, S2[2*q+1]));
                yc = fma2v(rq1.x, S2[2*q+2], yc);
                S2[2*q+2] = mul2(wq1.x, fma2v(kq1.x, v2, S2[2*q+2]));
                yd = fma2v(rq1.y, S2[2*q+3], yd);
                S2[2*q+3] = mul2(wq1.y, fma2v(kq1.y, v2, S2[2*q+3]));
            }
        }

        float y0, y1, y2, y3, y4, y5, y6, y7;
        unpk2(ya, y0, y1); unpk2(yb, y2, y3);
        unpk2(yc, y4, y5); unpk2(yd, y6, y7);
        float y = ((y0 + y1) + (y2 + y3)) + ((y4 + y5) + (y6 + y7));

        int tr = dir ? (Tq - 1 - t) : t;
        size_t off = base + (size_t)tr * Dq + j;
        if (dir == 0) g_yf[off] = y;
        else          g_yb[off] = y;
    }
}

// ---------------- groupnorm + output gate + silu-gate (→ z hi/lo) ---------------
__global__ void __launch_bounds__(128) gn_kernel(const float* __restrict__ ln_w,
                                                 const float* __restrict__ ln_b)
{
    int gidx = blockIdx.x * 4 + (threadIdx.x >> 5);
    int lane = threadIdx.x & 31;
    int bt = gidx / Hq, h = gidx % Hq;
    size_t rowbase = (size_t)bt * Dq + (size_t)h * Kq;
    size_t i0 = rowbase + lane, i1 = rowbase + lane + 32;

    float a = (g_yf[i0] + g_yb[i0]) * g_gate[i0];
    float c = (g_yf[i1] + g_yb[i1]) * g_gate[i1];
    float s = a + c, sq = a * a + c * c;
    #pragma unroll
    for (int o = 16; o; o >>= 1) {
        s  += __shfl_xor_sync(0xffffffffu, s,  o);
        sq += __shfl_xor_sync(0xffffffffu, sq, o);
    }
    float mean = s * (1.f / 64.f);
    float var  = sq * (1.f / 64.f) - mean * mean;
    float rstd = rsqrtf(var + 6.4e-4f);
    int d0 = h * Kq + lane, d1 = d0 + 32;
    float z0 = ((a - mean) * rstd * ln_w[d0] + ln_b[d0]) * g_g[i0];
    float z1 = ((c - mean) * rstd * ln_w[d1] + ln_b[d1]) * g_g[i1];
    __nv_bfloat16 h0 = __float2bfloat16(z0);
    __nv_bfloat16 h1 = __float2bfloat16(z1);
    g_zh[i0] = h0; g_zl[i0] = __float2bfloat16(z0 - __bfloat162float(h0));
    g_zh[i1] = h1; g_zl[i1] = __float2bfloat16(z1 - __bfloat162float(h1));
}

// ---------------- launch --------------------------------------------------------
extern "C" void kernel_launch(void* const* d_in, const int* in_sizes, int n_in,
                              void* d_out, int out_size)
{
    const float* x          = (const float*)d_in[0];
    const float* conv_w     = (const float*)d_in[1];
    const float* maa_x      = (const float*)d_in[2];
    const float* maa_w      = (const float*)d_in[3];
    const float* maa_k      = (const float*)d_in[4];
    const float* maa_v      = (const float*)d_in[5];
    const float* maa_r      = (const float*)d_in[6];
    const float* maa_g      = (const float*)d_in[7];
    const float* maa_w1     = (const float*)d_in[8];
    const float* maa_w2     = (const float*)d_in[9];
    const float* time_decay = (const float*)d_in[10];
    const float* decay_w1   = (const float*)d_in[11];
    const float* decay_w2   = (const float*)d_in[12];
    const float* Wr         = (const float*)d_in[13];
    const float* Wk         = (const float*)d_in[14];
    const float* Wv         = (const float*)d_in[15];
    const float* Wg         = (const float*)d_in[16];
    const float* Wo         = (const float*)d_in[17];
    const float* ln_w       = (const float*)d_in[18];
    const float* ln_b       = (const float*)d_in[19];
    const float* gate_w     = (const float*)d_in[20];
    const float* gate_b     = (const float*)d_in[21];
    float* out = (float*)d_out;

    float *p_t5, *p_xw, *p_r, *p_k, *p_v, *p_g, *p_h, *p_ww, *p_gate;
    __nv_bfloat16 *p_xxh, *p_xxl, *p_dxh, *p_dxl, *p_xkh, *p_xkl, *p_xvh, *p_xvl;
    __nv_bfloat16 *p_xrh, *p_xrl, *p_xgh, *p_xgl, *p_zh, *p_zl, *p_wh, *p_wl;
    __nv_bfloat16 *p_w1h, *p_w1l;
    cudaGetSymbolAddress((void**)&p_t5,   g_t5);
    cudaGetSymbolAddress((void**)&p_xw,   g_xw);
    cudaGetSymbolAddress((void**)&p_r,    g_r);
    cudaGetSymbolAddress((void**)&p_k,    g_k);
    cudaGetSymbolAddress((void**)&p_v,    g_v);
    cudaGetSymbolAddress((void**)&p_g,    g_g);
    cudaGetSymbolAddress((void**)&p_h,    g_hbuf);
    cudaGetSymbolAddress((void**)&p_ww,   g_ww);
    cudaGetSymbolAddress((void**)&p_gate, g_gate);
    cudaGetSymbolAddress((void**)&p_xxh,  g_xxh);
    cudaGetSymbolAddress((void**)&p_xxl,  g_xxl);
    cudaGetSymbolAddress((void**)&p_dxh,  g_dxh);
    cudaGetSymbolAddress((void**)&p_dxl,  g_dxl);
    cudaGetSymbolAddress((void**)&p_xkh,  g_xkh);
    cudaGetSymbolAddress((void**)&p_xkl,  g_xkl);
    cudaGetSymbolAddress((void**)&p_xvh,  g_xvh);
    cudaGetSymbolAddress((void**)&p_xvl,  g_xvl);
    cudaGetSymbolAddress((void**)&p_xrh,  g_xrh);
    cudaGetSymbolAddress((void**)&p_xrl,  g_xrl);
    cudaGetSymbolAddress((void**)&p_xgh,  g_xgh);
    cudaGetSymbolAddress((void**)&p_xgl,  g_xgl);
    cudaGetSymbolAddress((void**)&p_zh,   g_zh);
    cudaGetSymbolAddress((void**)&p_zl,   g_zl);
    cudaGetSymbolAddress((void**)&p_wh,   g_wh);
    cudaGetSymbolAddress((void**)&p_wl,   g_wl);
    cudaGetSymbolAddress((void**)&p_w1h,  g_w1h);
    cudaGetSymbolAddress((void**)&p_w1l,  g_w1l);

    cudaFuncSetAttribute((const void*)hmma_gemm<TEPI_NONE,3>, cudaFuncAttributeMaxDynamicSharedMemorySize, HM_SMEM);
    cudaFuncSetAttribute((const void*)hmma_gemm<TEPI_SILU,3>, cudaFuncAttributeMaxDynamicSharedMemorySize, HM_SMEM);
    cudaFuncSetAttribute((const void*)hmma_gemm<TEPI_GATE,3>, cudaFuncAttributeMaxDynamicSharedMemorySize, HM_SMEM);
    cudaFuncSetAttribute((const void*)hmma_gemm<TEPI_TANH,4>, cudaFuncAttributeMaxDynamicSharedMemorySize, HM_SMEM);

    // 0) conv / dx fp32+hi/lo / xxx hi/lo
    {
        int threads = 256;
        int blocks  = (int)((BTDq + threads - 1) / threads);
        conv_kernel<<<blocks, threads>>>(x, conv_w, maa_x);
    }

    // 1) weight transpose + split
    {
        dim3 g(32, 32, 6);
        wsplit_kernel<<<g, 256>>>(Wr, Wk, Wv, Wg, gate_w, Wo);
    }
    // 2) maa_w1 transpose + split
    {
        dim3 g(5, 32);
        wsplit_w1_kernel<<<g, 256>>>(maa_w1);
    }

    dim3 blk(256);
    dim3 grid_64(1, Mq / BMt);
    dim3 grid_dec(Dq / BNt, Mq / BMt);
    dim3 hm_grid(8, Mq / 128);
    dim3 hm_t5(2, Mq / 128);

    // 3) t5 = tanh(xxx @ maa_w1)  [HMMA 4-pass, N=160]
    hmma_gemm<TEPI_TANH,4><<<hm_t5, 256, HM_SMEM>>>(p_xxh, p_xxl, p_w1h, p_w1l,
                                                    p_t5, nullptr, 160, 160);

    // 4) fused token-mix: xw fp32 (exact dx); xk/xv/xr/xg as bf16 hi/lo
    {
        dim3 g(Dq / 128, Mq / 64);
        mix5_kernel<<<g, 256>>>(maa_w2, x, maa_w, maa_k, maa_v, maa_r, maa_g);
    }

    const size_t WS = 1024 * 1024;
    // 5) big projections (3-pass; fp32 dx anchors accuracy per R4/R13 evidence)
    hmma_gemm<TEPI_NONE,3><<<hm_grid, 256, HM_SMEM>>>(p_xrh, p_xrl, p_wh + 0*WS, p_wl + 0*WS, p_r, nullptr, 1024, 1024);
    hmma_gemm<TEPI_NONE,3><<<hm_grid, 256, HM_SMEM>>>(p_xkh, p_xkl, p_wh + 1*WS, p_wl + 1*WS, p_k, nullptr, 1024, 1024);
    hmma_gemm<TEPI_NONE,3><<<hm_grid, 256, HM_SMEM>>>(p_xvh, p_xvl, p_wh + 2*WS, p_wl + 2*WS, p_v, nullptr, 1024, 1024);
    hmma_gemm<TEPI_SILU,3><<<hm_grid, 256, HM_SMEM>>>(p_xgh, p_xgl, p_wh + 3*WS, p_wl + 3*WS, p_g, nullptr, 1024, 1024);
    hmma_gemm<TEPI_GATE,3><<<hm_grid, 256, HM_SMEM>>>(p_dxh, p_dxl, p_wh + 4*WS, p_wl + 4*WS, p_gate, gate_b, 1024, 1024);

    // 6) decay MLP (scalar fp32 for precision)
    sgemm<EPI_TANH><<<grid_64, blk>>>(p_xw, Dq, decay_w1, 64, p_h, 64,
                                      64, Dq, nullptr);
    sgemm<EPI_DECAY><<<grid_dec, blk>>>(p_h, 64, decay_w2, Dq, p_ww, Dq,
                                        Dq, 64, time_decay);

    // 7) bidirectional recurrence
    {
        dim3 g(Bq * Hq, 2);
        wkv_kernel<<<g, 64>>>();
    }

    // 8) gate + groupnorm + silu-gate → z hi/lo
    gn_kernel<<<(Mq * Hq) / 4, 128>>>(ln_w, ln_b);

    // 9) out = z @ Wo (HMMA 3-pass)
    hmma_gemm<TEPI_NONE,3><<<hm_grid, 256, HM_SMEM>>>(p_zh, p_zl, p_wh + 5*WS, p_wl + 5*WS, out, nullptr, 1024, 1024);
}